// round 1
// baseline (speedup 1.0000x reference)
#include <cuda_runtime.h>
#include <cstdint>
#include <math.h>

// Problem constants (fixed shapes from setup_inputs)
#define BB 2
#define CC 64
#define HH 64
#define WW 64
#define LL 4096   // H*W

// Scratch: score matrix S[b][l][k], 2*4096*4096 floats = 128 MiB
__device__ float g_S[(size_t)BB * LL * LL];
__device__ float g_invn[BB * LL];
__device__ int   g_flag[LL];

// ---------------------------------------------------------------------------
// Kernel 0: copy former+latter into out channels [0,128), zero shift [128,192)
// ---------------------------------------------------------------------------
__global__ void k_init_out(const float* __restrict__ x, float* __restrict__ out) {
    int idx = blockIdx.x * blockDim.x + threadIdx.x;
    const int total = BB * 192 * LL;
    if (idx >= total) return;
    int b  = idx / (192 * LL);
    int r  = idx - b * (192 * LL);
    int ch = r >> 12;        // /4096
    int l  = r & (LL - 1);
    float v = 0.0f;
    if (ch < 128) v = x[((size_t)b * 128 + ch) * LL + l];
    out[idx] = v;
}

// ---------------------------------------------------------------------------
// Kernel 1: per-(b,k) inverse norm of latter column, and flags from mask
// ---------------------------------------------------------------------------
__global__ void k_prep(const float* __restrict__ x, const float* __restrict__ mask) {
    int t = blockIdx.x * blockDim.x + threadIdx.x;  // 0..BB*LL-1
    if (t >= BB * LL) return;
    int b = t >> 12;
    int k = t & (LL - 1);
    const float* lat = x + ((size_t)b * 128 + 64) * LL;
    float s = 0.0f;
    #pragma unroll
    for (int c = 0; c < CC; c++) {
        float v = lat[(size_t)c * LL + k];
        s += v * v;
    }
    g_invn[t] = 1.0f / fmaxf(sqrtf(s), 1e-4f);
    if (t < LL) g_flag[t] = (mask[t] > 0.5f) ? 1 : 0;
}

// ---------------------------------------------------------------------------
// Kernel 2: score GEMM  S[b][l][k] = sum_c lat[b,c,l] * lat[b,c,k] * invn[b,k]
// Tiled 128x128, K=64 (two 32-chunks), 256 threads, 8x8 micro-tile.
// ---------------------------------------------------------------------------
#define BM 128
#define BN 128
#define BKK 32

__global__ __launch_bounds__(256) void k_gemm(const float* __restrict__ x) {
    int b  = blockIdx.z;
    int m0 = blockIdx.y * BM;  // l rows
    int n0 = blockIdx.x * BN;  // k cols
    const float* lat  = x + ((size_t)b * 128 + 64) * LL;
    const float* invn = g_invn + b * LL;

    __shared__ float As[BKK][BM];  // [c][l]
    __shared__ float Bs[BKK][BN];  // [c][k] (pre-scaled by invn)

    float acc[8][8];
    #pragma unroll
    for (int i = 0; i < 8; i++)
        #pragma unroll
        for (int j = 0; j < 8; j++) acc[i][j] = 0.0f;

    int tid = threadIdx.x;
    int tx = tid & 15;   // col group
    int ty = tid >> 4;   // row group

    #pragma unroll
    for (int k0 = 0; k0 < CC; k0 += BKK) {
        #pragma unroll
        for (int i = 0; i < (BKK * BM) / 256; i++) {
            int idx = tid + i * 256;
            int c = idx >> 7;
            int m = idx & 127;
            As[c][m] = lat[(size_t)(k0 + c) * LL + m0 + m];
        }
        #pragma unroll
        for (int i = 0; i < (BKK * BN) / 256; i++) {
            int idx = tid + i * 256;
            int c = idx >> 7;
            int n = idx & 127;
            Bs[c][n] = lat[(size_t)(k0 + c) * LL + n0 + n] * invn[n0 + n];
        }
        __syncthreads();

        #pragma unroll
        for (int c = 0; c < BKK; c++) {
            float a[8], bb[8];
            // split-half reads: lanes 0..15 hit 16 distinct 16B words -> conflict-free
            *(float4*)&a[0]  = *(const float4*)&As[c][ty * 4];
            *(float4*)&a[4]  = *(const float4*)&As[c][64 + ty * 4];
            *(float4*)&bb[0] = *(const float4*)&Bs[c][tx * 4];
            *(float4*)&bb[4] = *(const float4*)&Bs[c][64 + tx * 4];
            #pragma unroll
            for (int i = 0; i < 8; i++)
                #pragma unroll
                for (int j = 0; j < 8; j++)
                    acc[i][j] += a[i] * bb[j];
        }
        __syncthreads();
    }

    float* Sp = g_S + (size_t)b * LL * LL;
    #pragma unroll
    for (int i = 0; i < 8; i++) {
        int m = m0 + ((i < 4) ? (ty * 4 + i) : (64 + ty * 4 + (i - 4)));
        float* rowp = Sp + (size_t)m * LL + n0;
        float4 v0 = make_float4(acc[i][0], acc[i][1], acc[i][2], acc[i][3]);
        float4 v1 = make_float4(acc[i][4], acc[i][5], acc[i][6], acc[i][7]);
        *(float4*)&rowp[tx * 4]      = v0;
        *(float4*)&rowp[64 + tx * 4] = v1;
    }
}

// ---------------------------------------------------------------------------
// Kernel 3: per flagged row l: fused 9-point gather from S, masked softmax,
//           then GEMV against former; write shift output column.
// ---------------------------------------------------------------------------
__global__ __launch_bounds__(256) void k_attn(const float* __restrict__ x,
                                              float* __restrict__ out) {
    int l = blockIdx.x;
    int b = blockIdx.y;
    if (!g_flag[l]) return;

    __shared__ float row[LL];
    __shared__ float red[256];

    const float* S = g_S + (size_t)b * LL * LL;
    int tid = threadIdx.x;

    // row-side shifted indices (w-major shift by d2, flat-boundary semantics)
    int hl = l >> 6, wl = l & 63;
    int ml = (wl << 6) | hl;
    int  l2arr[3];
    bool v2[3];
    #pragma unroll
    for (int d2i = 0; d2i < 3; d2i++) {
        int m2 = ml + d2i - 1;
        bool v = (m2 >= 0 && m2 < LL);
        v2[d2i] = v;
        l2arr[d2i] = v ? (((m2 & 63) << 6) | (m2 >> 6)) : 0;
    }

    float mx = -INFINITY;
    for (int k = tid; k < LL; k += 256) {
        float acc = 0.0f;
        int hk = k >> 6, wk = k & 63;
        int mk = (wk << 6) | hk;
        #pragma unroll
        for (int d2i = 0; d2i < 3; d2i++) {
            if (!v2[d2i]) continue;
            int mk2 = mk + d2i - 1;
            if (mk2 < 0 || mk2 >= LL) continue;
            int k2  = ((mk2 & 63) << 6) | (mk2 >> 6);
            int l2v = l2arr[d2i];
            #pragma unroll
            for (int d1 = -1; d1 <= 1; d1++) {
                int r = l2v + d1;
                int c = k2 + d1;
                if (r >= 0 && r < LL && c >= 0 && c < LL)
                    acc += S[(size_t)r * LL + c];
            }
        }
        float val = g_flag[k] ? -INFINITY : acc;
        row[k] = val;
        mx = fmaxf(mx, val);
    }

    // block max
    red[tid] = mx;
    __syncthreads();
    #pragma unroll
    for (int s = 128; s > 0; s >>= 1) {
        if (tid < s) red[tid] = fmaxf(red[tid], red[tid + s]);
        __syncthreads();
    }
    mx = red[0];
    __syncthreads();

    // exp + sum
    float sum = 0.0f;
    for (int k = tid; k < LL; k += 256) {
        float v = row[k];
        float e = (v == -INFINITY) ? 0.0f : __expf(v - mx);
        row[k] = e;
        sum += e;
    }
    red[tid] = sum;
    __syncthreads();
    #pragma unroll
    for (int s = 128; s > 0; s >>= 1) {
        if (tid < s) red[tid] += red[tid + s];
        __syncthreads();
    }
    sum = red[0];
    __syncthreads();
    float inv = 1.0f / sum;

    // GEMV: out_shift[b, ch, l] = inv * sum_k row[k] * former[b, ch, k]
    int wid  = tid >> 5;
    int lane = tid & 31;
    #pragma unroll
    for (int cs = 0; cs < 8; cs++) {
        int ch = wid * 8 + cs;
        const float* F = x + ((size_t)b * 128 + ch) * LL;
        float s = 0.0f;
        for (int k = lane; k < LL; k += 32) s += row[k] * F[k];
        #pragma unroll
        for (int o = 16; o > 0; o >>= 1) s += __shfl_down_sync(0xFFFFFFFFu, s, o);
        if (lane == 0)
            out[((size_t)b * 192 + 128 + ch) * LL + l] = s * inv;
    }
}

// ---------------------------------------------------------------------------
extern "C" void kernel_launch(void* const* d_in, const int* in_sizes, int n_in,
                              void* d_out, int out_size) {
    const float* x    = (const float*)d_in[0];   // (2,128,64,64)
    const float* mask = (const float*)d_in[1];   // (1,1,64,64)
    float* out = (float*)d_out;                  // (2,192,64,64)

    {
        int total = BB * 192 * LL;
        k_init_out<<<(total + 255) / 256, 256>>>(x, out);
    }
    {
        int total = BB * LL;
        k_prep<<<(total + 255) / 256, 256>>>(x, mask);
    }
    {
        dim3 grid(LL / BN, LL / BM, BB);
        k_gemm<<<grid, 256>>>(x);
    }
    {
        dim3 grid(LL, BB);
        k_attn<<<grid, 256>>>(x, out);
    }
}

// round 2
// speedup vs baseline: 1.1911x; 1.1911x over previous
#include <cuda_runtime.h>
#include <cstdint>
#include <math.h>

// Problem constants (fixed shapes from setup_inputs)
#define BB 2
#define CC 64
#define LL 4096   // H*W = 64*64

// Scratch
__device__ float g_S[(size_t)BB * LL * LL];   // score matrix, 128 MiB
__device__ float g_P[(size_t)BB * LL * LL];   // compacted attn rows
__device__ float g_invn[BB * LL];
__device__ int   g_flag[LL];
__device__ int   g_list[LL];
__device__ int   g_nflag;

// packed fp32x2 FMA (Blackwell FFMA2)
__device__ __forceinline__ void ffma2(unsigned long long &d, unsigned long long a,
                                      unsigned long long b) {
    asm("fma.rn.f32x2 %0, %1, %2, %0;" : "+l"(d) : "l"(a), "l"(b));
}

// ---------------------------------------------------------------------------
// Kernel 0: copy former+latter into out channels [0,128), zero shift [128,192)
// ---------------------------------------------------------------------------
__global__ void k_init_out(const float* __restrict__ x, float* __restrict__ out) {
    int idx = blockIdx.x * blockDim.x + threadIdx.x;
    const int total = BB * 192 * LL;
    if (idx >= total) return;
    int b  = idx / (192 * LL);
    int r  = idx - b * (192 * LL);
    int ch = r >> 12;
    int l  = r & (LL - 1);
    float v = 0.0f;
    if (ch < 128) v = x[((size_t)b * 128 + ch) * LL + l];
    out[idx] = v;
}

// ---------------------------------------------------------------------------
// Kernel 1: per-(b,k) inverse norm of latter column, and flags from mask
// ---------------------------------------------------------------------------
__global__ void k_prep(const float* __restrict__ x, const float* __restrict__ mask) {
    int t = blockIdx.x * blockDim.x + threadIdx.x;
    if (t >= BB * LL) return;
    int b = t >> 12;
    int k = t & (LL - 1);
    const float* lat = x + ((size_t)b * 128 + 64) * LL;
    float s = 0.0f;
    #pragma unroll
    for (int c = 0; c < CC; c++) {
        float v = lat[(size_t)c * LL + k];
        s += v * v;
    }
    g_invn[t] = 1.0f / fmaxf(sqrtf(s), 1e-4f);
    if (t < LL) g_flag[t] = (mask[t] > 0.5f) ? 1 : 0;
}

// ---------------------------------------------------------------------------
// Kernel 1b: deterministic compaction of flagged indices (single block)
// ---------------------------------------------------------------------------
__global__ void k_compact() {
    __shared__ int cnt[256];
    int t = threadIdx.x;
    int base_l = t * 16;
    int c = 0;
    #pragma unroll
    for (int j = 0; j < 16; j++) c += g_flag[base_l + j];
    cnt[t] = c;
    __syncthreads();
    for (int off = 1; off < 256; off <<= 1) {
        int v = (t >= off) ? cnt[t - off] : 0;
        __syncthreads();
        cnt[t] += v;
        __syncthreads();
    }
    int pos = cnt[t] - c;  // exclusive prefix
    for (int j = 0; j < 16; j++) {
        int l = base_l + j;
        if (g_flag[l]) g_list[pos++] = l;
    }
    if (t == 255) g_nflag = cnt[255];
}

// ---------------------------------------------------------------------------
// Kernel 2: score GEMM  S[b][l][k] = sum_c lat[b,c,l] * lat[b,c,k] * invn[b,k]
// 128x128 tile, packed f32x2 FMA. A values duplicated in smem so LDS.64 gives
// (a,a) pairs directly; B pairs are naturally adjacent.
// ---------------------------------------------------------------------------
#define BM 128
#define BN 128
#define BKK 32

__global__ __launch_bounds__(256) void k_gemm(const float* __restrict__ x) {
    int b  = blockIdx.z;
    int m0 = blockIdx.y * BM;
    int n0 = blockIdx.x * BN;
    const float* lat  = x + ((size_t)b * 128 + 64) * LL;
    const float* invn = g_invn + b * LL;

    __shared__ float As2[BKK][2 * BM];  // duplicated: As2[c][2m]=As2[c][2m+1]=A
    __shared__ float Bs[BKK][BN];

    unsigned long long acc2[8][4];
    #pragma unroll
    for (int i = 0; i < 8; i++)
        #pragma unroll
        for (int j = 0; j < 4; j++) acc2[i][j] = 0ULL;

    int tid = threadIdx.x;
    int tx = tid & 15;
    int ty = tid >> 4;

    #pragma unroll
    for (int k0 = 0; k0 < CC; k0 += BKK) {
        #pragma unroll
        for (int i = 0; i < (BKK * BM) / 256; i++) {
            int idx = tid + i * 256;
            int c = idx >> 7;
            int m = idx & 127;
            float v = lat[(size_t)(k0 + c) * LL + m0 + m];
            *(float2*)&As2[c][2 * m] = make_float2(v, v);
        }
        #pragma unroll
        for (int i = 0; i < (BKK * BN) / 256; i++) {
            int idx = tid + i * 256;
            int c = idx >> 7;
            int n = idx & 127;
            Bs[c][n] = lat[(size_t)(k0 + c) * LL + n0 + n] * invn[n0 + n];
        }
        __syncthreads();

        #pragma unroll
        for (int c = 0; c < BKK; c++) {
            unsigned long long av[8], bv[4];
            #pragma unroll
            for (int i = 0; i < 4; i++)
                av[i] = *(const unsigned long long*)&As2[c][2 * (ty * 4 + i)];
            #pragma unroll
            for (int i = 0; i < 4; i++)
                av[4 + i] = *(const unsigned long long*)&As2[c][2 * (64 + ty * 4 + i)];
            #pragma unroll
            for (int j = 0; j < 2; j++)
                bv[j] = *(const unsigned long long*)&Bs[c][tx * 4 + 2 * j];
            #pragma unroll
            for (int j = 0; j < 2; j++)
                bv[2 + j] = *(const unsigned long long*)&Bs[c][64 + tx * 4 + 2 * j];
            #pragma unroll
            for (int i = 0; i < 8; i++)
                #pragma unroll
                for (int j = 0; j < 4; j++)
                    ffma2(acc2[i][j], av[i], bv[j]);
        }
        __syncthreads();
    }

    float* Sp = g_S + (size_t)b * LL * LL;
    #pragma unroll
    for (int i = 0; i < 8; i++) {
        int m = m0 + ((i < 4) ? (ty * 4 + i) : (64 + ty * 4 + (i - 4)));
        float* rowp = Sp + (size_t)m * LL + n0;
        float2 p0 = *(float2*)&acc2[i][0];
        float2 p1 = *(float2*)&acc2[i][1];
        float2 p2 = *(float2*)&acc2[i][2];
        float2 p3 = *(float2*)&acc2[i][3];
        *(float4*)&rowp[tx * 4]      = make_float4(p0.x, p0.y, p1.x, p1.y);
        *(float4*)&rowp[64 + tx * 4] = make_float4(p2.x, p2.y, p3.x, p3.y);
    }
}

// ---------------------------------------------------------------------------
// Kernel 3: per flagged row (compact index ii): 9-point gather + masked
// softmax; write normalized attn row to g_P[b][ii][*].
// ---------------------------------------------------------------------------
__global__ __launch_bounds__(256) void k_softmax() {
    int ii = blockIdx.x;
    if (ii >= g_nflag) return;
    int l = g_list[ii];
    int b = blockIdx.y;

    __shared__ float row[LL];
    __shared__ float red[256];

    const float* S = g_S + (size_t)b * LL * LL;
    int tid = threadIdx.x;

    int hl = l >> 6, wl = l & 63;
    int ml = (wl << 6) | hl;
    int  l2arr[3];
    bool v2[3];
    #pragma unroll
    for (int d2i = 0; d2i < 3; d2i++) {
        int m2 = ml + d2i - 1;
        bool v = (m2 >= 0 && m2 < LL);
        v2[d2i] = v;
        l2arr[d2i] = v ? (((m2 & 63) << 6) | (m2 >> 6)) : 0;
    }

    float mx = -INFINITY;
    for (int k = tid; k < LL; k += 256) {
        float acc = 0.0f;
        int hk = k >> 6, wk = k & 63;
        int mk = (wk << 6) | hk;
        #pragma unroll
        for (int d2i = 0; d2i < 3; d2i++) {
            if (!v2[d2i]) continue;
            int mk2 = mk + d2i - 1;
            if (mk2 < 0 || mk2 >= LL) continue;
            int k2  = ((mk2 & 63) << 6) | (mk2 >> 6);
            int l2v = l2arr[d2i];
            #pragma unroll
            for (int d1 = -1; d1 <= 1; d1++) {
                int r = l2v + d1;
                int c = k2 + d1;
                if (r >= 0 && r < LL && c >= 0 && c < LL)
                    acc += S[(size_t)r * LL + c];
            }
        }
        float val = g_flag[k] ? -INFINITY : acc;
        row[k] = val;
        mx = fmaxf(mx, val);
    }

    red[tid] = mx;
    __syncthreads();
    #pragma unroll
    for (int s = 128; s > 0; s >>= 1) {
        if (tid < s) red[tid] = fmaxf(red[tid], red[tid + s]);
        __syncthreads();
    }
    mx = red[0];
    __syncthreads();

    float sum = 0.0f;
    for (int k = tid; k < LL; k += 256) {
        float v = row[k];
        float e = (v == -INFINITY) ? 0.0f : __expf(v - mx);
        row[k] = e;
        sum += e;
    }
    red[tid] = sum;
    __syncthreads();
    #pragma unroll
    for (int s = 128; s > 0; s >>= 1) {
        if (tid < s) red[tid] += red[tid + s];
        __syncthreads();
    }
    float inv = 1.0f / red[0];
    __syncthreads();

    float* Pp = g_P + ((size_t)b * LL + ii) * LL;
    for (int k = tid; k < LL; k += 256)
        Pp[k] = row[k] * inv;
}

// ---------------------------------------------------------------------------
// Kernel 4: shift GEMM. out_shift[b, ch, list[i]] = sum_k P[b,i,k]*former[b,ch,k]
// Tile: 64 ch x 8 rows, K staged through smem in 128-chunks. FMA-bound.
// ---------------------------------------------------------------------------
__global__ __launch_bounds__(256) void k_shift(const float* __restrict__ x,
                                               float* __restrict__ out) {
    int i0 = blockIdx.x * 8;
    int b  = blockIdx.y;
    int nf = g_nflag;
    if (i0 >= nf) return;
    int nvalid = min(8, nf - i0);

    __shared__ float Fs[64][132];  // [ch][kk], pad keeps 16B alignment, no conflicts
    __shared__ float Ps[8][132];

    int tid  = threadIdx.x;
    int wid  = tid >> 5;
    int lane = tid & 31;

    float acc[8][8];
    #pragma unroll
    for (int i = 0; i < 8; i++)
        #pragma unroll
        for (int j = 0; j < 8; j++) acc[i][j] = 0.0f;

    const float* F = x + (size_t)b * 128 * LL;             // former channels
    const float* P = g_P + ((size_t)b * LL + i0) * LL;

    for (int k0 = 0; k0 < LL; k0 += 128) {
        #pragma unroll
        for (int i = 0; i < 8; i++) {           // 64ch x 128kk = 8192 floats
            int e  = (tid + i * 256) * 4;
            int ch = e >> 7;
            int kk = e & 127;
            float4 v = *(const float4*)&F[(size_t)ch * LL + k0 + kk];
            *(float4*)&Fs[ch][kk] = v;
        }
        {
            int e  = tid * 4;                   // 8 x 128 = 1024 floats
            int ir = e >> 7;
            int kk = e & 127;
            float4 v = make_float4(0.f, 0.f, 0.f, 0.f);
            if (ir < nvalid) v = *(const float4*)&P[(size_t)ir * LL + k0 + kk];
            *(float4*)&Ps[ir][kk] = v;
        }
        __syncthreads();

        #pragma unroll
        for (int jj = 0; jj < 4; jj++) {
            int kk = lane + jj * 32;
            float f[8], p[8];
            #pragma unroll
            for (int cs = 0; cs < 8; cs++) f[cs] = Fs[wid * 8 + cs][kk];
            #pragma unroll
            for (int ir = 0; ir < 8; ir++) p[ir] = Ps[ir][kk];
            #pragma unroll
            for (int cs = 0; cs < 8; cs++)
                #pragma unroll
                for (int ir = 0; ir < 8; ir++)
                    acc[cs][ir] += f[cs] * p[ir];
        }
        __syncthreads();
    }

    #pragma unroll
    for (int cs = 0; cs < 8; cs++) {
        #pragma unroll
        for (int ir = 0; ir < 8; ir++) {
            float v = acc[cs][ir];
            #pragma unroll
            for (int o = 16; o > 0; o >>= 1)
                v += __shfl_down_sync(0xFFFFFFFFu, v, o);
            if (lane == 0 && ir < nvalid) {
                int l = g_list[i0 + ir];
                out[((size_t)b * 192 + 128 + wid * 8 + cs) * LL + l] = v;
            }
        }
    }
}

// ---------------------------------------------------------------------------
extern "C" void kernel_launch(void* const* d_in, const int* in_sizes, int n_in,
                              void* d_out, int out_size) {
    const float* x    = (const float*)d_in[0];   // (2,128,64,64)
    const float* mask = (const float*)d_in[1];   // (1,1,64,64)
    float* out = (float*)d_out;                  // (2,192,64,64)

    {
        int total = BB * 192 * LL;
        k_init_out<<<(total + 255) / 256, 256>>>(x, out);
    }
    {
        int total = BB * LL;
        k_prep<<<(total + 255) / 256, 256>>>(x, mask);
    }
    k_compact<<<1, 256>>>();
    {
        dim3 grid(LL / BN, LL / BM, BB);
        k_gemm<<<grid, 256>>>(x);
    }
    {
        dim3 grid(LL, BB);
        k_softmax<<<grid, 256>>>();
    }
    {
        dim3 grid(LL / 8, BB);
        k_shift<<<grid, 256>>>(x, out);
    }
}

// round 3
// speedup vs baseline: 1.2723x; 1.0682x over previous
#include <cuda_runtime.h>
#include <cstdint>
#include <math.h>

// Problem constants (fixed shapes from setup_inputs)
#define BB 2
#define CC 64
#define LL 4096   // H*W = 64*64

// Scratch
__device__ float g_S[(size_t)BB * LL * LL];   // score matrix, 128 MiB
__device__ float g_P[(size_t)BB * LL * LL];   // compacted attn rows
__device__ float g_invn[BB * LL];
__device__ int   g_flag[LL];
__device__ int   g_list[LL];
__device__ int   g_nflag;

// packed fp32x2 FMA (Blackwell FFMA2)
__device__ __forceinline__ void ffma2(unsigned long long &d, unsigned long long a,
                                      unsigned long long b) {
    asm("fma.rn.f32x2 %0, %1, %2, %0;" : "+l"(d) : "l"(a), "l"(b));
}

// ---------------------------------------------------------------------------
// Kernel 0: copy former+latter into out channels [0,128), zero shift [128,192)
// ---------------------------------------------------------------------------
__global__ void k_init_out(const float* __restrict__ x, float* __restrict__ out) {
    int idx = blockIdx.x * blockDim.x + threadIdx.x;
    const int total = BB * 192 * LL;
    if (idx >= total) return;
    int b  = idx / (192 * LL);
    int r  = idx - b * (192 * LL);
    int ch = r >> 12;
    int l  = r & (LL - 1);
    float v = 0.0f;
    if (ch < 128) v = x[((size_t)b * 128 + ch) * LL + l];
    out[idx] = v;
}

// ---------------------------------------------------------------------------
// Kernel 1: per-(b,k) inverse norm of latter column, and flags from mask
// ---------------------------------------------------------------------------
__global__ void k_prep(const float* __restrict__ x, const float* __restrict__ mask) {
    int t = blockIdx.x * blockDim.x + threadIdx.x;
    if (t >= BB * LL) return;
    int b = t >> 12;
    int k = t & (LL - 1);
    const float* lat = x + ((size_t)b * 128 + 64) * LL;
    float s = 0.0f;
    #pragma unroll
    for (int c = 0; c < CC; c++) {
        float v = lat[(size_t)c * LL + k];
        s += v * v;
    }
    g_invn[t] = 1.0f / fmaxf(sqrtf(s), 1e-4f);
    if (t < LL) g_flag[t] = (mask[t] > 0.5f) ? 1 : 0;
}

// ---------------------------------------------------------------------------
// Kernel 1b: deterministic compaction of flagged indices (single block)
// ---------------------------------------------------------------------------
__global__ void k_compact() {
    __shared__ int cnt[256];
    int t = threadIdx.x;
    int base_l = t * 16;
    int c = 0;
    #pragma unroll
    for (int j = 0; j < 16; j++) c += g_flag[base_l + j];
    cnt[t] = c;
    __syncthreads();
    for (int off = 1; off < 256; off <<= 1) {
        int v = (t >= off) ? cnt[t - off] : 0;
        __syncthreads();
        cnt[t] += v;
        __syncthreads();
    }
    int pos = cnt[t] - c;  // exclusive prefix
    for (int j = 0; j < 16; j++) {
        int l = base_l + j;
        if (g_flag[l]) g_list[pos++] = l;
    }
    if (t == 255) g_nflag = cnt[255];
}

// ---------------------------------------------------------------------------
// Kernel 2: symmetric score GEMM.
// G[l][k] = sum_c lat[c,l]*lat[c,k] is symmetric; compute only upper tiles
// (tm <= tn, 528 of 1024) and write:
//   S[m][n] = G[m][n] * invn[n]   (normal, from registers)
//   S[n][m] = G[m][n] * invn[m]   (transposed, smem-staged, skip if tm==tn)
// 128x128 tile, FFMA2 inner, 2 CTAs/SM via launch_bounds.
// ---------------------------------------------------------------------------
#define BM 128
#define BN 128
#define BKK 32
#define NT 32          // tiles per dim (4096/128)

__global__ __launch_bounds__(256, 2) void k_gemm(const float* __restrict__ x) {
    __shared__ float sm_all[BKK * 256 + BKK * BN];   // As2 | Bs (48 KB); Ts aliases As2
    float* As2 = sm_all;                 // [BKK][256] duplicated A
    float* Bs  = sm_all + BKK * 256;     // [BKK][128] raw B

    int b = blockIdx.y;
    // decode upper-triangular tile index
    int tt = blockIdx.x, tm = 0;
    while (tt >= NT - tm) { tt -= NT - tm; tm++; }
    int tn = tm + tt;
    int m0 = tm * BM, n0 = tn * BN;

    const float* lat  = x + ((size_t)b * 128 + 64) * LL;
    const float* invn = g_invn + b * LL;

    unsigned long long acc2[8][4];
    #pragma unroll
    for (int i = 0; i < 8; i++)
        #pragma unroll
        for (int j = 0; j < 4; j++) acc2[i][j] = 0ULL;

    int tid = threadIdx.x;
    int tx = tid & 15;
    int ty = tid >> 4;

    for (int k0 = 0; k0 < CC; k0 += BKK) {
        #pragma unroll
        for (int i = 0; i < (BKK * BM) / 256; i++) {
            int idx = tid + i * 256;
            int c = idx >> 7;
            int m = idx & 127;
            float v = lat[(size_t)(k0 + c) * LL + m0 + m];
            *(float2*)&As2[c * 256 + 2 * m] = make_float2(v, v);
        }
        #pragma unroll
        for (int i = 0; i < (BKK * BN) / 256; i++) {
            int idx = tid + i * 256;
            int c = idx >> 7;
            int n = idx & 127;
            Bs[c * 128 + n] = lat[(size_t)(k0 + c) * LL + n0 + n];
        }
        __syncthreads();

        #pragma unroll
        for (int c = 0; c < BKK; c++) {
            unsigned long long av[8], bv[4];
            #pragma unroll
            for (int i = 0; i < 4; i++)
                av[i] = *(const unsigned long long*)&As2[c * 256 + 2 * (ty * 4 + i)];
            #pragma unroll
            for (int i = 0; i < 4; i++)
                av[4 + i] = *(const unsigned long long*)&As2[c * 256 + 2 * (64 + ty * 4 + i)];
            #pragma unroll
            for (int j = 0; j < 2; j++)
                bv[j] = *(const unsigned long long*)&Bs[c * 128 + tx * 4 + 2 * j];
            #pragma unroll
            for (int j = 0; j < 2; j++)
                bv[2 + j] = *(const unsigned long long*)&Bs[c * 128 + 64 + tx * 4 + 2 * j];
            #pragma unroll
            for (int i = 0; i < 8; i++)
                #pragma unroll
                for (int j = 0; j < 4; j++)
                    ffma2(acc2[i][j], av[i], bv[j]);
        }
        __syncthreads();
    }

    float* Sp = g_S + (size_t)b * LL * LL;

    // ---- normal-side store, scaled by invn[n] ----
    {
        float4 w0 = *(const float4*)&invn[n0 + tx * 4];
        float4 w1 = *(const float4*)&invn[n0 + 64 + tx * 4];
        #pragma unroll
        for (int i = 0; i < 8; i++) {
            int m = m0 + ((i < 4) ? (ty * 4 + i) : (64 + ty * 4 + (i - 4)));
            float* rowp = Sp + (size_t)m * LL + n0;
            float2 p0 = *(float2*)&acc2[i][0];
            float2 p1 = *(float2*)&acc2[i][1];
            float2 p2 = *(float2*)&acc2[i][2];
            float2 p3 = *(float2*)&acc2[i][3];
            *(float4*)&rowp[tx * 4] =
                make_float4(p0.x * w0.x, p0.y * w0.y, p1.x * w0.z, p1.y * w0.w);
            *(float4*)&rowp[64 + tx * 4] =
                make_float4(p2.x * w1.x, p2.y * w1.y, p3.x * w1.z, p3.y * w1.w);
        }
    }

    // ---- transposed-side store, scaled by invn[m] (skip on diagonal) ----
    if (tm != tn) {
        float* Ts = sm_all;           // [32][132] staging, aliases As2
        int r  = tid >> 3;            // 0..31
        int c0 = (tid & 7) * 16;      // col base, 16 floats per thread
        #pragma unroll
        for (int q = 0; q < 4; q++) {
            __syncthreads();
            if ((tx >> 3) == (q & 1)) {
                int half = q >> 1;
                int txl  = tx - (q & 1) * 8;
                #pragma unroll
                for (int i = 0; i < 8; i++) {
                    int ml = (i < 4) ? (ty * 4 + i) : (64 + ty * 4 + (i - 4));
                    #pragma unroll
                    for (int j = 0; j < 4; j++) {
                        float g = ((float*)&acc2[i][half * 2 + (j >> 1)])[j & 1];
                        Ts[(txl * 4 + j) * 132 + ml] = g;
                    }
                }
            }
            __syncthreads();
            #pragma unroll
            for (int u = 0; u < 4; u++) {
                int c = c0 + u * 4;
                float4 g4 = *(float4*)&Ts[r * 132 + c];
                float4 w  = *(const float4*)&invn[m0 + c];
                g4.x *= w.x; g4.y *= w.y; g4.z *= w.z; g4.w *= w.w;
                *(float4*)&Sp[(size_t)(n0 + q * 32 + r) * LL + m0 + c] = g4;
            }
        }
    }
}

// ---------------------------------------------------------------------------
// Kernel 3: per flagged row (compact index ii): 9-point gather + masked
// softmax; write normalized attn row to g_P[b][ii][*].
// ---------------------------------------------------------------------------
__global__ __launch_bounds__(256) void k_softmax() {
    int ii = blockIdx.x;
    if (ii >= g_nflag) return;
    int l = g_list[ii];
    int b = blockIdx.y;

    __shared__ float row[LL];
    __shared__ float red[256];

    const float* S = g_S + (size_t)b * LL * LL;
    int tid = threadIdx.x;

    int hl = l >> 6, wl = l & 63;
    int ml = (wl << 6) | hl;
    int  l2arr[3];
    bool v2[3];
    #pragma unroll
    for (int d2i = 0; d2i < 3; d2i++) {
        int m2 = ml + d2i - 1;
        bool v = (m2 >= 0 && m2 < LL);
        v2[d2i] = v;
        l2arr[d2i] = v ? (((m2 & 63) << 6) | (m2 >> 6)) : 0;
    }

    float mx = -INFINITY;
    for (int k = tid; k < LL; k += 256) {
        float acc = 0.0f;
        int hk = k >> 6, wk = k & 63;
        int mk = (wk << 6) | hk;
        #pragma unroll
        for (int d2i = 0; d2i < 3; d2i++) {
            if (!v2[d2i]) continue;
            int mk2 = mk + d2i - 1;
            if (mk2 < 0 || mk2 >= LL) continue;
            int k2  = ((mk2 & 63) << 6) | (mk2 >> 6);
            int l2v = l2arr[d2i];
            #pragma unroll
            for (int d1 = -1; d1 <= 1; d1++) {
                int r = l2v + d1;
                int c = k2 + d1;
                if (r >= 0 && r < LL && c >= 0 && c < LL)
                    acc += S[(size_t)r * LL + c];
            }
        }
        float val = g_flag[k] ? -INFINITY : acc;
        row[k] = val;
        mx = fmaxf(mx, val);
    }

    red[tid] = mx;
    __syncthreads();
    #pragma unroll
    for (int s = 128; s > 0; s >>= 1) {
        if (tid < s) red[tid] = fmaxf(red[tid], red[tid + s]);
        __syncthreads();
    }
    mx = red[0];
    __syncthreads();

    float sum = 0.0f;
    for (int k = tid; k < LL; k += 256) {
        float v = row[k];
        float e = (v == -INFINITY) ? 0.0f : __expf(v - mx);
        row[k] = e;
        sum += e;
    }
    red[tid] = sum;
    __syncthreads();
    #pragma unroll
    for (int s = 128; s > 0; s >>= 1) {
        if (tid < s) red[tid] += red[tid + s];
        __syncthreads();
    }
    float inv = 1.0f / red[0];
    __syncthreads();

    float* Pp = g_P + ((size_t)b * LL + ii) * LL;
    for (int k = tid; k < LL; k += 256)
        Pp[k] = row[k] * inv;
}

// ---------------------------------------------------------------------------
// Kernel 4: shift GEMM. out_shift[b, ch, list[i]] = sum_k P[b,i,k]*former[b,ch,k]
// Tile: 64 ch x 8 rows, K staged through smem in 128-chunks.
// ---------------------------------------------------------------------------
__global__ __launch_bounds__(256) void k_shift(const float* __restrict__ x,
                                               float* __restrict__ out) {
    int i0 = blockIdx.x * 8;
    int b  = blockIdx.y;
    int nf = g_nflag;
    if (i0 >= nf) return;
    int nvalid = min(8, nf - i0);

    __shared__ float Fs[64][132];
    __shared__ float Ps[8][132];

    int tid  = threadIdx.x;
    int wid  = tid >> 5;
    int lane = tid & 31;

    float acc[8][8];
    #pragma unroll
    for (int i = 0; i < 8; i++)
        #pragma unroll
        for (int j = 0; j < 8; j++) acc[i][j] = 0.0f;

    const float* F = x + (size_t)b * 128 * LL;
    const float* P = g_P + ((size_t)b * LL + i0) * LL;

    for (int k0 = 0; k0 < LL; k0 += 128) {
        #pragma unroll
        for (int i = 0; i < 8; i++) {
            int e  = (tid + i * 256) * 4;
            int ch = e >> 7;
            int kk = e & 127;
            float4 v = *(const float4*)&F[(size_t)ch * LL + k0 + kk];
            *(float4*)&Fs[ch][kk] = v;
        }
        {
            int e  = tid * 4;
            int ir = e >> 7;
            int kk = e & 127;
            float4 v = make_float4(0.f, 0.f, 0.f, 0.f);
            if (ir < nvalid) v = *(const float4*)&P[(size_t)ir * LL + k0 + kk];
            *(float4*)&Ps[ir][kk] = v;
        }
        __syncthreads();

        #pragma unroll
        for (int jj = 0; jj < 4; jj++) {
            int kk = lane + jj * 32;
            float f[8], p[8];
            #pragma unroll
            for (int cs = 0; cs < 8; cs++) f[cs] = Fs[wid * 8 + cs][kk];
            #pragma unroll
            for (int ir = 0; ir < 8; ir++) p[ir] = Ps[ir][kk];
            #pragma unroll
            for (int cs = 0; cs < 8; cs++)
                #pragma unroll
                for (int ir = 0; ir < 8; ir++)
                    acc[cs][ir] += f[cs] * p[ir];
        }
        __syncthreads();
    }

    #pragma unroll
    for (int cs = 0; cs < 8; cs++) {
        #pragma unroll
        for (int ir = 0; ir < 8; ir++) {
            float v = acc[cs][ir];
            #pragma unroll
            for (int o = 16; o > 0; o >>= 1)
                v += __shfl_down_sync(0xFFFFFFFFu, v, o);
            if (lane == 0 && ir < nvalid) {
                int l = g_list[i0 + ir];
                out[((size_t)b * 192 + 128 + wid * 8 + cs) * LL + l] = v;
            }
        }
    }
}

// ---------------------------------------------------------------------------
extern "C" void kernel_launch(void* const* d_in, const int* in_sizes, int n_in,
                              void* d_out, int out_size) {
    const float* x    = (const float*)d_in[0];   // (2,128,64,64)
    const float* mask = (const float*)d_in[1];   // (1,1,64,64)
    float* out = (float*)d_out;                  // (2,192,64,64)

    {
        int total = BB * 192 * LL;
        k_init_out<<<(total + 255) / 256, 256>>>(x, out);
    }
    {
        int total = BB * LL;
        k_prep<<<(total + 255) / 256, 256>>>(x, mask);
    }
    k_compact<<<1, 256>>>();
    {
        dim3 grid(NT * (NT + 1) / 2, BB);   // 528 upper tiles per batch
        k_gemm<<<grid, 256>>>(x);
    }
    {
        dim3 grid(LL, BB);
        k_softmax<<<grid, 256>>>();
    }
    {
        dim3 grid(LL / 8, BB);
        k_shift<<<grid, 256>>>(x, out);
    }
}

// round 5
// speedup vs baseline: 1.4894x; 1.1707x over previous
#include <cuda_runtime.h>
#include <cuda_bf16.h>
#include <cstdint>
#include <math.h>

// Problem constants (fixed shapes from setup_inputs)
#define BB 2
#define CC 64
#define LL 4096   // H*W = 64*64

// Scratch
__device__ float g_S[(size_t)BB * LL * LL];   // score matrix, 128 MiB
__device__ float g_P[(size_t)BB * LL * LL];   // compacted attn rows
__device__ float g_invn[BB * LL];
__device__ int   g_flag[LL];
__device__ int   g_list[LL];
__device__ int   g_nflag;

// ---------------------------------------------------------------------------
// mma.sync helpers (arch-agnostic: sm_80+ PTX, no tcgen05)
// ---------------------------------------------------------------------------
__device__ __forceinline__ uint32_t smem_u32(const void* p) {
    uint32_t a;
    asm("{ .reg .u64 t; cvta.to.shared.u64 t, %1; cvt.u32.u64 %0, t; }"
        : "=r"(a) : "l"(p));
    return a;
}
__device__ __forceinline__ void ldsm_x4(uint32_t* r, uint32_t addr) {
    asm volatile("ldmatrix.sync.aligned.m8n8.x4.shared.b16 {%0,%1,%2,%3}, [%4];"
                 : "=r"(r[0]), "=r"(r[1]), "=r"(r[2]), "=r"(r[3]) : "r"(addr));
}
__device__ __forceinline__ void mma_bf16(float* d, const uint32_t* a, const uint32_t* b) {
    asm volatile(
        "mma.sync.aligned.m16n8k16.row.col.f32.bf16.bf16.f32 "
        "{%0,%1,%2,%3}, {%4,%5,%6,%7}, {%8,%9}, {%0,%1,%2,%3};"
        : "+f"(d[0]), "+f"(d[1]), "+f"(d[2]), "+f"(d[3])
        : "r"(a[0]), "r"(a[1]), "r"(a[2]), "r"(a[3]), "r"(b[0]), "r"(b[1]));
}
#define SW128(o) ((o) ^ (((o) >> 3) & 0x70))

// ---------------------------------------------------------------------------
// Kernel 0: copy former+latter into out channels [0,128), zero shift [128,192)
// ---------------------------------------------------------------------------
__global__ void k_init_out(const float* __restrict__ x, float* __restrict__ out) {
    int idx = blockIdx.x * blockDim.x + threadIdx.x;
    const int total = BB * 192 * LL;
    if (idx >= total) return;
    int b  = idx / (192 * LL);
    int r  = idx - b * (192 * LL);
    int ch = r >> 12;
    int l  = r & (LL - 1);
    float v = 0.0f;
    if (ch < 128) v = x[((size_t)b * 128 + ch) * LL + l];
    out[idx] = v;
}

// ---------------------------------------------------------------------------
// Kernel 1: per-(b,k) inverse norm of latter column, and flags from mask
// ---------------------------------------------------------------------------
__global__ void k_prep(const float* __restrict__ x, const float* __restrict__ mask) {
    int t = blockIdx.x * blockDim.x + threadIdx.x;
    if (t >= BB * LL) return;
    int b = t >> 12;
    int k = t & (LL - 1);
    const float* lat = x + ((size_t)b * 128 + 64) * LL;
    float s = 0.0f;
    #pragma unroll
    for (int c = 0; c < CC; c++) {
        float v = lat[(size_t)c * LL + k];
        s += v * v;
    }
    g_invn[t] = 1.0f / fmaxf(sqrtf(s), 1e-4f);
    if (t < LL) g_flag[t] = (mask[t] > 0.5f) ? 1 : 0;
}

// ---------------------------------------------------------------------------
// Kernel 1b: deterministic compaction of flagged indices (single block)
// ---------------------------------------------------------------------------
__global__ void k_compact() {
    __shared__ int cnt[256];
    int t = threadIdx.x;
    int base_l = t * 16;
    int c = 0;
    #pragma unroll
    for (int j = 0; j < 16; j++) c += g_flag[base_l + j];
    cnt[t] = c;
    __syncthreads();
    for (int off = 1; off < 256; off <<= 1) {
        int v = (t >= off) ? cnt[t - off] : 0;
        __syncthreads();
        cnt[t] += v;
        __syncthreads();
    }
    int pos = cnt[t] - c;
    for (int j = 0; j < 16; j++) {
        int l = base_l + j;
        if (g_flag[l]) g_list[pos++] = l;
    }
    if (t == 255) g_nflag = cnt[255];
}

// ---------------------------------------------------------------------------
// Kernel 2: mma.sync bf16x3 score GEMM.
// S[m][n] = (sum_c lat[c,m]*lat[c,n]) * invn[n], computed as
// hi*hi + hi*lo + lo*hi in bf16 HMMA with fp32 accumulation.
// Block = 128x128 tile, 8 warps (each 32m x 64n), K=64 resident in smem.
// ---------------------------------------------------------------------------
#define SM_AHI    0
#define SM_ALO    16384
#define SM_BHI    32768
#define SM_BLO    49152
#define SM_INVN   65536
#define SM_DYN    66048

__global__ __launch_bounds__(256) void k_gemm_mma(const float* __restrict__ x) {
    extern __shared__ char smem[];
    uint32_t sbase = smem_u32(smem);
    int tid  = threadIdx.x;
    int n0 = blockIdx.x * 128;
    int m0 = blockIdx.y * 128;
    int b  = blockIdx.z;

    const float* lat = x + ((size_t)b * 128 + 64) * LL;
    float* invn_s = (float*)(smem + SM_INVN);
    if (tid < 128) invn_s[tid] = g_invn[b * LL + n0 + tid];

    // ---- load + split-convert: threads 0-127 do A rows (m), 128-255 B rows (n)
    {
        int side = tid >> 7;                  // 0 = A, 1 = B
        int r    = tid & 127;
        const float* src = lat + (side ? n0 : m0) + r;
        char* dhi = smem + (side ? SM_BHI : SM_AHI);
        char* dlo = smem + (side ? SM_BLO : SM_ALO);
        #pragma unroll 8
        for (int c0 = 0; c0 < CC; c0 += 2) {
            float v0 = src[(size_t)c0 * LL];
            float v1 = src[(size_t)(c0 + 1) * LL];
            unsigned short h0 = __bfloat16_as_ushort(__float2bfloat16(v0));
            unsigned short h1 = __bfloat16_as_ushort(__float2bfloat16(v1));
            unsigned short l0 = __bfloat16_as_ushort(__float2bfloat16(
                v0 - __bfloat162float(__ushort_as_bfloat16(h0))));
            unsigned short l1 = __bfloat16_as_ushort(__float2bfloat16(
                v1 - __bfloat162float(__ushort_as_bfloat16(h1))));
            uint32_t off = SW128((uint32_t)(r * 128 + c0 * 2));
            *(uint32_t*)(dhi + off) = (uint32_t)h0 | ((uint32_t)h1 << 16);
            *(uint32_t*)(dlo + off) = (uint32_t)l0 | ((uint32_t)l1 << 16);
        }
    }
    __syncthreads();

    int wid  = tid >> 5;
    int lane = tid & 31;
    int wm = (wid & 3) * 32;    // warp m offset within tile
    int wn = (wid >> 2) * 64;   // warp n offset within tile
    int j  = lane & 7;
    int g  = lane >> 3;

    float acc[2][8][4];
    #pragma unroll
    for (int mi = 0; mi < 2; mi++)
        #pragma unroll
        for (int t = 0; t < 8; t++)
            #pragma unroll
            for (int q = 0; q < 4; q++) acc[mi][t][q] = 0.0f;

    #pragma unroll
    for (int kc = 0; kc < 4; kc++) {
        int kb = kc * 32;   // byte offset of k-chunk (16 bf16)

        uint32_t a_hi[2][4], a_lo[2][4], b_hi[4][4], b_lo[4][4];
        #pragma unroll
        for (int mi = 0; mi < 2; mi++) {
            // lanes: g0=(m+j,k0) g1=(m+8+j,k0) g2=(m+j,k8) g3=(m+8+j,k8)
            uint32_t row = wm + mi * 16 + (g & 1) * 8 + j;
            uint32_t kby = kb + (g >> 1) * 16;
            uint32_t off = SW128(row * 128 + kby);
            ldsm_x4(a_hi[mi], sbase + SM_AHI + off);
            ldsm_x4(a_lo[mi], sbase + SM_ALO + off);
        }
        #pragma unroll
        for (int tp = 0; tp < 4; tp++) {
            // lanes: g0=(n+j,k0) g1=(n+j,k8) g2=(n+8+j,k0) g3=(n+8+j,k8)
            uint32_t row = wn + tp * 16 + (g >> 1) * 8 + j;
            uint32_t kby = kb + (g & 1) * 16;
            uint32_t off = SW128(row * 128 + kby);
            ldsm_x4(b_hi[tp], sbase + SM_BHI + off);
            ldsm_x4(b_lo[tp], sbase + SM_BLO + off);
        }

        #pragma unroll
        for (int mi = 0; mi < 2; mi++)
            #pragma unroll
            for (int t = 0; t < 8; t++) {
                const uint32_t* bh = &b_hi[t >> 1][(t & 1) * 2];
                const uint32_t* bl = &b_lo[t >> 1][(t & 1) * 2];
                mma_bf16(acc[mi][t], a_hi[mi], bh);
                mma_bf16(acc[mi][t], a_hi[mi], bl);
                mma_bf16(acc[mi][t], a_lo[mi], bh);
            }
    }

    // ---- epilogue: *invn[n], store (32B sectors, fully utilized)
    float* Sp = g_S + (size_t)b * LL * LL;
    #pragma unroll
    for (int t = 0; t < 8; t++) {
        int n = wn + t * 8 + (lane & 3) * 2;
        float2 w = *(float2*)&invn_s[n];
        #pragma unroll
        for (int mi = 0; mi < 2; mi++) {
            int r0 = m0 + wm + mi * 16 + (lane >> 2);
            float* p0 = &Sp[(size_t)r0 * LL + n0 + n];
            float* p1 = &Sp[(size_t)(r0 + 8) * LL + n0 + n];
            *(float2*)p0 = make_float2(acc[mi][t][0] * w.x, acc[mi][t][1] * w.y);
            *(float2*)p1 = make_float2(acc[mi][t][2] * w.x, acc[mi][t][3] * w.y);
        }
    }
}

// ---------------------------------------------------------------------------
// Kernel 3: per flagged row (compact index ii): 9-point gather + masked
// softmax; write normalized attn row to g_P[b][ii][*].
// ---------------------------------------------------------------------------
__global__ __launch_bounds__(256) void k_softmax() {
    int ii = blockIdx.x;
    if (ii >= g_nflag) return;
    int l = g_list[ii];
    int b = blockIdx.y;

    __shared__ float row[LL];
    __shared__ float red[256];

    const float* S = g_S + (size_t)b * LL * LL;
    int tid = threadIdx.x;

    int hl = l >> 6, wl = l & 63;
    int ml = (wl << 6) | hl;
    int  l2arr[3];
    bool v2[3];
    #pragma unroll
    for (int d2i = 0; d2i < 3; d2i++) {
        int m2 = ml + d2i - 1;
        bool v = (m2 >= 0 && m2 < LL);
        v2[d2i] = v;
        l2arr[d2i] = v ? (((m2 & 63) << 6) | (m2 >> 6)) : 0;
    }

    float mx = -INFINITY;
    for (int k = tid; k < LL; k += 256) {
        float acc = 0.0f;
        int hk = k >> 6, wk = k & 63;
        int mk = (wk << 6) | hk;
        #pragma unroll
        for (int d2i = 0; d2i < 3; d2i++) {
            if (!v2[d2i]) continue;
            int mk2 = mk + d2i - 1;
            if (mk2 < 0 || mk2 >= LL) continue;
            int k2  = ((mk2 & 63) << 6) | (mk2 >> 6);
            int l2v = l2arr[d2i];
            #pragma unroll
            for (int d1 = -1; d1 <= 1; d1++) {
                int r = l2v + d1;
                int c = k2 + d1;
                if (r >= 0 && r < LL && c >= 0 && c < LL)
                    acc += S[(size_t)r * LL + c];
            }
        }
        float val = g_flag[k] ? -INFINITY : acc;
        row[k] = val;
        mx = fmaxf(mx, val);
    }

    red[tid] = mx;
    __syncthreads();
    #pragma unroll
    for (int s = 128; s > 0; s >>= 1) {
        if (tid < s) red[tid] = fmaxf(red[tid], red[tid + s]);
        __syncthreads();
    }
    mx = red[0];
    __syncthreads();

    float sum = 0.0f;
    for (int k = tid; k < LL; k += 256) {
        float v = row[k];
        float e = (v == -INFINITY) ? 0.0f : __expf(v - mx);
        row[k] = e;
        sum += e;
    }
    red[tid] = sum;
    __syncthreads();
    #pragma unroll
    for (int s = 128; s > 0; s >>= 1) {
        if (tid < s) red[tid] += red[tid + s];
        __syncthreads();
    }
    float inv = 1.0f / red[0];
    __syncthreads();

    float* Pp = g_P + ((size_t)b * LL + ii) * LL;
    for (int k = tid; k < LL; k += 256)
        Pp[k] = row[k] * inv;
}

// ---------------------------------------------------------------------------
// Kernel 4: shift GEMM. out_shift[b, ch, list[i]] = sum_k P[b,i,k]*former[b,ch,k]
// ---------------------------------------------------------------------------
__global__ __launch_bounds__(256) void k_shift(const float* __restrict__ x,
                                               float* __restrict__ out) {
    int i0 = blockIdx.x * 8;
    int b  = blockIdx.y;
    int nf = g_nflag;
    if (i0 >= nf) return;
    int nvalid = min(8, nf - i0);

    __shared__ float Fs[64][132];
    __shared__ float Ps[8][132];

    int tid  = threadIdx.x;
    int wid  = tid >> 5;
    int lane = tid & 31;

    float acc[8][8];
    #pragma unroll
    for (int i = 0; i < 8; i++)
        #pragma unroll
        for (int j = 0; j < 8; j++) acc[i][j] = 0.0f;

    const float* F = x + (size_t)b * 128 * LL;
    const float* P = g_P + ((size_t)b * LL + i0) * LL;

    for (int k0 = 0; k0 < LL; k0 += 128) {
        #pragma unroll
        for (int i = 0; i < 8; i++) {
            int e  = (tid + i * 256) * 4;
            int ch = e >> 7;
            int kk = e & 127;
            float4 v = *(const float4*)&F[(size_t)ch * LL + k0 + kk];
            *(float4*)&Fs[ch][kk] = v;
        }
        {
            int e  = tid * 4;
            int ir = e >> 7;
            int kk = e & 127;
            float4 v = make_float4(0.f, 0.f, 0.f, 0.f);
            if (ir < nvalid) v = *(const float4*)&P[(size_t)ir * LL + k0 + kk];
            *(float4*)&Ps[ir][kk] = v;
        }
        __syncthreads();

        #pragma unroll
        for (int jj = 0; jj < 4; jj++) {
            int kk = lane + jj * 32;
            float f[8], p[8];
            #pragma unroll
            for (int cs = 0; cs < 8; cs++) f[cs] = Fs[wid * 8 + cs][kk];
            #pragma unroll
            for (int ir = 0; ir < 8; ir++) p[ir] = Ps[ir][kk];
            #pragma unroll
            for (int cs = 0; cs < 8; cs++)
                #pragma unroll
                for (int ir = 0; ir < 8; ir++)
                    acc[cs][ir] += f[cs] * p[ir];
        }
        __syncthreads();
    }

    #pragma unroll
    for (int cs = 0; cs < 8; cs++) {
        #pragma unroll
        for (int ir = 0; ir < 8; ir++) {
            float v = acc[cs][ir];
            #pragma unroll
            for (int o = 16; o > 0; o >>= 1)
                v += __shfl_down_sync(0xFFFFFFFFu, v, o);
            if (lane == 0 && ir < nvalid) {
                int l = g_list[i0 + ir];
                out[((size_t)b * 192 + 128 + wid * 8 + cs) * LL + l] = v;
            }
        }
    }
}

// ---------------------------------------------------------------------------
extern "C" void kernel_launch(void* const* d_in, const int* in_sizes, int n_in,
                              void* d_out, int out_size) {
    const float* x    = (const float*)d_in[0];   // (2,128,64,64)
    const float* mask = (const float*)d_in[1];   // (1,1,64,64)
    float* out = (float*)d_out;                  // (2,192,64,64)

    {
        int total = BB * 192 * LL;
        k_init_out<<<(total + 255) / 256, 256>>>(x, out);
    }
    {
        int total = BB * LL;
        k_prep<<<(total + 255) / 256, 256>>>(x, mask);
    }
    k_compact<<<1, 256>>>();
    {
        cudaFuncSetAttribute(k_gemm_mma, cudaFuncAttributeMaxDynamicSharedMemorySize, SM_DYN);
        dim3 grid(LL / 128, LL / 128, BB);   // 32 x 32 x 2 tiles
        k_gemm_mma<<<grid, 256, SM_DYN>>>(x);
    }
    {
        dim3 grid(LL, BB);
        k_softmax<<<grid, 256>>>();
    }
    {
        dim3 grid(LL / 8, BB);
        k_shift<<<grid, 256>>>(x, out);
    }
}

// round 6
// speedup vs baseline: 1.5405x; 1.0343x over previous
#include <cuda_runtime.h>
#include <cuda_bf16.h>
#include <cstdint>
#include <math.h>

// Problem constants (fixed shapes from setup_inputs)
#define BB 2
#define CC 64
#define LL 4096   // H*W = 64*64

// Scratch
__device__ float g_S[(size_t)BB * LL * LL];   // score matrix, 128 MiB
__device__ float g_P[(size_t)BB * LL * LL];   // compacted attn rows
__device__ float g_invn[BB * LL];
__device__ int   g_flag[LL];
__device__ int   g_list[LL];
__device__ int   g_nflag;

// ---------------------------------------------------------------------------
// mma.sync helpers (arch-agnostic: sm_80+ PTX, no tcgen05)
// ---------------------------------------------------------------------------
__device__ __forceinline__ uint32_t smem_u32(const void* p) {
    uint32_t a;
    asm("{ .reg .u64 t; cvta.to.shared.u64 t, %1; cvt.u32.u64 %0, t; }"
        : "=r"(a) : "l"(p));
    return a;
}
__device__ __forceinline__ void ldsm_x4(uint32_t* r, uint32_t addr) {
    asm volatile("ldmatrix.sync.aligned.m8n8.x4.shared.b16 {%0,%1,%2,%3}, [%4];"
                 : "=r"(r[0]), "=r"(r[1]), "=r"(r[2]), "=r"(r[3]) : "r"(addr));
}
__device__ __forceinline__ void mma_bf16(float* d, const uint32_t* a, const uint32_t* b) {
    asm volatile(
        "mma.sync.aligned.m16n8k16.row.col.f32.bf16.bf16.f32 "
        "{%0,%1,%2,%3}, {%4,%5,%6,%7}, {%8,%9}, {%0,%1,%2,%3};"
        : "+f"(d[0]), "+f"(d[1]), "+f"(d[2]), "+f"(d[3])
        : "r"(a[0]), "r"(a[1]), "r"(a[2]), "r"(a[3]), "r"(b[0]), "r"(b[1]));
}
#define SW128(o) ((o) ^ (((o) >> 3) & 0x70))

// ---------------------------------------------------------------------------
// Kernel 0: copy former+latter into out channels [0,128), zero shift [128,192)
// ---------------------------------------------------------------------------
__global__ void k_init_out(const float* __restrict__ x, float* __restrict__ out) {
    int idx = blockIdx.x * blockDim.x + threadIdx.x;
    const int total = BB * 192 * LL;
    if (idx >= total) return;
    int b  = idx / (192 * LL);
    int r  = idx - b * (192 * LL);
    int ch = r >> 12;
    int l  = r & (LL - 1);
    float v = 0.0f;
    if (ch < 128) v = x[((size_t)b * 128 + ch) * LL + l];
    out[idx] = v;
}

// ---------------------------------------------------------------------------
// Kernel 1: per-(b,k) inverse norm of latter column, and flags from mask
// ---------------------------------------------------------------------------
__global__ void k_prep(const float* __restrict__ x, const float* __restrict__ mask) {
    int t = blockIdx.x * blockDim.x + threadIdx.x;
    if (t >= BB * LL) return;
    int b = t >> 12;
    int k = t & (LL - 1);
    const float* lat = x + ((size_t)b * 128 + 64) * LL;
    float s = 0.0f;
    #pragma unroll
    for (int c = 0; c < CC; c++) {
        float v = lat[(size_t)c * LL + k];
        s += v * v;
    }
    g_invn[t] = 1.0f / fmaxf(sqrtf(s), 1e-4f);
    if (t < LL) g_flag[t] = (mask[t] > 0.5f) ? 1 : 0;
}

// ---------------------------------------------------------------------------
// Kernel 1b: deterministic compaction of flagged indices (single block)
// ---------------------------------------------------------------------------
__global__ void k_compact() {
    __shared__ int cnt[256];
    int t = threadIdx.x;
    int base_l = t * 16;
    int c = 0;
    #pragma unroll
    for (int j = 0; j < 16; j++) c += g_flag[base_l + j];
    cnt[t] = c;
    __syncthreads();
    for (int off = 1; off < 256; off <<= 1) {
        int v = (t >= off) ? cnt[t - off] : 0;
        __syncthreads();
        cnt[t] += v;
        __syncthreads();
    }
    int pos = cnt[t] - c;
    for (int j = 0; j < 16; j++) {
        int l = base_l + j;
        if (g_flag[l]) g_list[pos++] = l;
    }
    if (t == 255) g_nflag = cnt[255];
}

// ---------------------------------------------------------------------------
// Kernel 2: mma.sync bf16x3 score GEMM.
// ---------------------------------------------------------------------------
#define SM_AHI    0
#define SM_ALO    16384
#define SM_BHI    32768
#define SM_BLO    49152
#define SM_INVN   65536
#define SM_DYN    66048

__global__ __launch_bounds__(256) void k_gemm_mma(const float* __restrict__ x) {
    extern __shared__ char smem[];
    uint32_t sbase = smem_u32(smem);
    int tid  = threadIdx.x;
    int n0 = blockIdx.x * 128;
    int m0 = blockIdx.y * 128;
    int b  = blockIdx.z;

    const float* lat = x + ((size_t)b * 128 + 64) * LL;
    float* invn_s = (float*)(smem + SM_INVN);
    if (tid < 128) invn_s[tid] = g_invn[b * LL + n0 + tid];

    {
        int side = tid >> 7;                  // 0 = A, 1 = B
        int r    = tid & 127;
        const float* src = lat + (side ? n0 : m0) + r;
        char* dhi = smem + (side ? SM_BHI : SM_AHI);
        char* dlo = smem + (side ? SM_BLO : SM_ALO);
        #pragma unroll 8
        for (int c0 = 0; c0 < CC; c0 += 2) {
            float v0 = src[(size_t)c0 * LL];
            float v1 = src[(size_t)(c0 + 1) * LL];
            unsigned short h0 = __bfloat16_as_ushort(__float2bfloat16(v0));
            unsigned short h1 = __bfloat16_as_ushort(__float2bfloat16(v1));
            unsigned short l0 = __bfloat16_as_ushort(__float2bfloat16(
                v0 - __bfloat162float(__ushort_as_bfloat16(h0))));
            unsigned short l1 = __bfloat16_as_ushort(__float2bfloat16(
                v1 - __bfloat162float(__ushort_as_bfloat16(h1))));
            uint32_t off = SW128((uint32_t)(r * 128 + c0 * 2));
            *(uint32_t*)(dhi + off) = (uint32_t)h0 | ((uint32_t)h1 << 16);
            *(uint32_t*)(dlo + off) = (uint32_t)l0 | ((uint32_t)l1 << 16);
        }
    }
    __syncthreads();

    int wid  = tid >> 5;
    int lane = tid & 31;
    int wm = (wid & 3) * 32;
    int wn = (wid >> 2) * 64;
    int j  = lane & 7;
    int g  = lane >> 3;

    float acc[2][8][4];
    #pragma unroll
    for (int mi = 0; mi < 2; mi++)
        #pragma unroll
        for (int t = 0; t < 8; t++)
            #pragma unroll
            for (int q = 0; q < 4; q++) acc[mi][t][q] = 0.0f;

    #pragma unroll
    for (int kc = 0; kc < 4; kc++) {
        int kb = kc * 32;

        uint32_t a_hi[2][4], a_lo[2][4], b_hi[4][4], b_lo[4][4];
        #pragma unroll
        for (int mi = 0; mi < 2; mi++) {
            uint32_t row = wm + mi * 16 + (g & 1) * 8 + j;
            uint32_t kby = kb + (g >> 1) * 16;
            uint32_t off = SW128(row * 128 + kby);
            ldsm_x4(a_hi[mi], sbase + SM_AHI + off);
            ldsm_x4(a_lo[mi], sbase + SM_ALO + off);
        }
        #pragma unroll
        for (int tp = 0; tp < 4; tp++) {
            uint32_t row = wn + tp * 16 + (g >> 1) * 8 + j;
            uint32_t kby = kb + (g & 1) * 16;
            uint32_t off = SW128(row * 128 + kby);
            ldsm_x4(b_hi[tp], sbase + SM_BHI + off);
            ldsm_x4(b_lo[tp], sbase + SM_BLO + off);
        }

        #pragma unroll
        for (int mi = 0; mi < 2; mi++)
            #pragma unroll
            for (int t = 0; t < 8; t++) {
                const uint32_t* bh = &b_hi[t >> 1][(t & 1) * 2];
                const uint32_t* bl = &b_lo[t >> 1][(t & 1) * 2];
                mma_bf16(acc[mi][t], a_hi[mi], bh);
                mma_bf16(acc[mi][t], a_hi[mi], bl);
                mma_bf16(acc[mi][t], a_lo[mi], bh);
            }
    }

    float* Sp = g_S + (size_t)b * LL * LL;
    #pragma unroll
    for (int t = 0; t < 8; t++) {
        int n = wn + t * 8 + (lane & 3) * 2;
        float2 w = *(float2*)&invn_s[n];
        #pragma unroll
        for (int mi = 0; mi < 2; mi++) {
            int r0 = m0 + wm + mi * 16 + (lane >> 2);
            float* p0 = &Sp[(size_t)r0 * LL + n0 + n];
            float* p1 = &Sp[(size_t)(r0 + 8) * LL + n0 + n];
            *(float2*)p0 = make_float2(acc[mi][t][0] * w.x, acc[mi][t][1] * w.y);
            *(float2*)p1 = make_float2(acc[mi][t][2] * w.x, acc[mi][t][3] * w.y);
        }
    }
}

// ---------------------------------------------------------------------------
// Kernel 3: per flagged row: 9-point FUSED gather (coalesced form) + masked
// softmax; write normalized attn row to g_P[b][ii][*].
//
// Index algebra: for output k (h=k>>6, w=k&63) and term (e in {-1,0,1},
// d1 in {-1,0,1}):  mk2 = w*64 + (h+e).
//   h+e in [0,64): k2 = (h+e)*64 + w        (contiguous in k)
//   h+e == -1   : valid iff w>=1,  k2 = 4032 + (w-1)
//   h+e == 64   : valid iff w<=62, k2 = w+1
// load column c = k2 + d1 (bounds-checked), row r = l2arr[e] + d1.
// All bulk accesses are coalesced shifted row reads.
// ---------------------------------------------------------------------------
__global__ __launch_bounds__(256) void k_softmax() {
    int ii = blockIdx.x;
    if (ii >= g_nflag) return;
    int l = g_list[ii];
    int b = blockIdx.y;

    __shared__ float row[LL];
    __shared__ float red[256];

    const float* S = g_S + (size_t)b * LL * LL;
    int tid = threadIdx.x;

    // row-side shifted indices (flat-boundary semantics)
    int hl = l >> 6, wl = l & 63;
    int ml = (wl << 6) | hl;

    // row pointers + validity for the 9 (e,d1) terms
    const float* rp[3][3];
    bool rv[3][3];
    #pragma unroll
    for (int ei = 0; ei < 3; ei++) {
        int m2 = ml + ei - 1;
        bool v = (m2 >= 0 && m2 < LL);
        int l2v = v ? (((m2 & 63) << 6) | (m2 >> 6)) : 0;
        #pragma unroll
        for (int di = 0; di < 3; di++) {
            int r = l2v + di - 1;
            bool ok = v && (r >= 0 && r < LL);
            rv[ei][di] = ok;
            rp[ei][di] = ok ? (S + (size_t)r * LL) : S;
        }
    }

    float mx = -INFINITY;
    #pragma unroll 4
    for (int k = tid; k < LL; k += 256) {
        int h = k >> 6, w = k & 63;
        float acc = 0.0f;
        #pragma unroll
        for (int ei = 0; ei < 3; ei++) {
            int hh = h + ei - 1;
            int k2;
            bool kv;
            if (hh >= 0 && hh < 64) { k2 = (hh << 6) | w; kv = true; }
            else if (hh < 0)        { k2 = 4032 + (w - 1); kv = (w >= 1); }
            else                    { k2 = w + 1;          kv = (w <= 62); }
            if (!kv) continue;
            #pragma unroll
            for (int di = 0; di < 3; di++) {
                int c = k2 + di - 1;
                if (rv[ei][di] && c >= 0 && c < LL)
                    acc += rp[ei][di][c];
            }
        }
        float val = g_flag[k] ? -INFINITY : acc;
        row[k] = val;
        mx = fmaxf(mx, val);
    }

    red[tid] = mx;
    __syncthreads();
    #pragma unroll
    for (int s = 128; s > 0; s >>= 1) {
        if (tid < s) red[tid] = fmaxf(red[tid], red[tid + s]);
        __syncthreads();
    }
    mx = red[0];
    __syncthreads();

    float sum = 0.0f;
    for (int k = tid; k < LL; k += 256) {
        float v = row[k];
        float e = (v == -INFINITY) ? 0.0f : __expf(v - mx);
        row[k] = e;
        sum += e;
    }
    red[tid] = sum;
    __syncthreads();
    #pragma unroll
    for (int s = 128; s > 0; s >>= 1) {
        if (tid < s) red[tid] += red[tid + s];
        __syncthreads();
    }
    float inv = 1.0f / red[0];
    __syncthreads();

    float* Pp = g_P + ((size_t)b * LL + ii) * LL;
    for (int k = tid; k < LL; k += 256)
        Pp[k] = row[k] * inv;
}

// ---------------------------------------------------------------------------
// Kernel 4: shift GEMM. out_shift[b, ch, list[i]] = sum_k P[b,i,k]*former[b,ch,k]
// ---------------------------------------------------------------------------
__global__ __launch_bounds__(256) void k_shift(const float* __restrict__ x,
                                               float* __restrict__ out) {
    int i0 = blockIdx.x * 8;
    int b  = blockIdx.y;
    int nf = g_nflag;
    if (i0 >= nf) return;
    int nvalid = min(8, nf - i0);

    __shared__ float Fs[64][132];
    __shared__ float Ps[8][132];

    int tid  = threadIdx.x;
    int wid  = tid >> 5;
    int lane = tid & 31;

    float acc[8][8];
    #pragma unroll
    for (int i = 0; i < 8; i++)
        #pragma unroll
        for (int j = 0; j < 8; j++) acc[i][j] = 0.0f;

    const float* F = x + (size_t)b * 128 * LL;
    const float* P = g_P + ((size_t)b * LL + i0) * LL;

    for (int k0 = 0; k0 < LL; k0 += 128) {
        #pragma unroll
        for (int i = 0; i < 8; i++) {
            int e  = (tid + i * 256) * 4;
            int ch = e >> 7;
            int kk = e & 127;
            float4 v = *(const float4*)&F[(size_t)ch * LL + k0 + kk];
            *(float4*)&Fs[ch][kk] = v;
        }
        {
            int e  = tid * 4;
            int ir = e >> 7;
            int kk = e & 127;
            float4 v = make_float4(0.f, 0.f, 0.f, 0.f);
            if (ir < nvalid) v = *(const float4*)&P[(size_t)ir * LL + k0 + kk];
            *(float4*)&Ps[ir][kk] = v;
        }
        __syncthreads();

        #pragma unroll
        for (int jj = 0; jj < 4; jj++) {
            int kk = lane + jj * 32;
            float f[8], p[8];
            #pragma unroll
            for (int cs = 0; cs < 8; cs++) f[cs] = Fs[wid * 8 + cs][kk];
            #pragma unroll
            for (int ir = 0; ir < 8; ir++) p[ir] = Ps[ir][kk];
            #pragma unroll
            for (int cs = 0; cs < 8; cs++)
                #pragma unroll
                for (int ir = 0; ir < 8; ir++)
                    acc[cs][ir] += f[cs] * p[ir];
        }
        __syncthreads();
    }

    #pragma unroll
    for (int cs = 0; cs < 8; cs++) {
        #pragma unroll
        for (int ir = 0; ir < 8; ir++) {
            float v = acc[cs][ir];
            #pragma unroll
            for (int o = 16; o > 0; o >>= 1)
                v += __shfl_down_sync(0xFFFFFFFFu, v, o);
            if (lane == 0 && ir < nvalid) {
                int l = g_list[i0 + ir];
                out[((size_t)b * 192 + 128 + wid * 8 + cs) * LL + l] = v;
            }
        }
    }
}

// ---------------------------------------------------------------------------
extern "C" void kernel_launch(void* const* d_in, const int* in_sizes, int n_in,
                              void* d_out, int out_size) {
    const float* x    = (const float*)d_in[0];   // (2,128,64,64)
    const float* mask = (const float*)d_in[1];   // (1,1,64,64)
    float* out = (float*)d_out;                  // (2,192,64,64)

    {
        int total = BB * 192 * LL;
        k_init_out<<<(total + 255) / 256, 256>>>(x, out);
    }
    {
        int total = BB * LL;
        k_prep<<<(total + 255) / 256, 256>>>(x, mask);
    }
    k_compact<<<1, 256>>>();
    {
        cudaFuncSetAttribute(k_gemm_mma, cudaFuncAttributeMaxDynamicSharedMemorySize, SM_DYN);
        dim3 grid(LL / 128, LL / 128, BB);
        k_gemm_mma<<<grid, 256, SM_DYN>>>(x);
    }
    {
        dim3 grid(LL, BB);
        k_softmax<<<grid, 256>>>();
    }
    {
        dim3 grid(LL / 8, BB);
        k_shift<<<grid, 256>>>(x, out);
    }
}

// round 7
// speedup vs baseline: 1.7116x; 1.1111x over previous
#include <cuda_runtime.h>
#include <cuda_bf16.h>
#include <cstdint>
#include <math.h>

// Problem constants (fixed shapes from setup_inputs)
#define BB 2
#define CC 64
#define LL 4096   // H*W = 64*64

// Scratch
__device__ float    g_S[(size_t)BB * LL * LL];          // score matrix, 128 MiB
__device__ uint32_t g_Pbh32[(size_t)BB * LL * LL / 2];  // attn rows bf16 hi (packed pairs)
__device__ uint32_t g_Pbl32[(size_t)BB * LL * LL / 2];  // attn rows bf16 lo
__device__ uint32_t g_Fbh32[(size_t)BB * 64 * LL / 2];  // former bf16 hi
__device__ uint32_t g_Fbl32[(size_t)BB * 64 * LL / 2];  // former bf16 lo
__device__ float    g_part[(size_t)BB * 4 * LL * 64];   // K-split partials, 8 MiB
__device__ float    g_invn[BB * LL];
__device__ int      g_flag[LL];
__device__ int      g_list[LL];
__device__ int      g_nflag;

// ---------------------------------------------------------------------------
// mma.sync helpers (arch-agnostic: sm_80+ PTX, no tcgen05)
// ---------------------------------------------------------------------------
__device__ __forceinline__ uint32_t smem_u32(const void* p) {
    uint32_t a;
    asm("{ .reg .u64 t; cvta.to.shared.u64 t, %1; cvt.u32.u64 %0, t; }"
        : "=r"(a) : "l"(p));
    return a;
}
__device__ __forceinline__ void ldsm_x4(uint32_t* r, uint32_t addr) {
    asm volatile("ldmatrix.sync.aligned.m8n8.x4.shared.b16 {%0,%1,%2,%3}, [%4];"
                 : "=r"(r[0]), "=r"(r[1]), "=r"(r[2]), "=r"(r[3]) : "r"(addr));
}
__device__ __forceinline__ void mma_bf16(float* d, const uint32_t* a, const uint32_t* b) {
    asm volatile(
        "mma.sync.aligned.m16n8k16.row.col.f32.bf16.bf16.f32 "
        "{%0,%1,%2,%3}, {%4,%5,%6,%7}, {%8,%9}, {%0,%1,%2,%3};"
        : "+f"(d[0]), "+f"(d[1]), "+f"(d[2]), "+f"(d[3])
        : "r"(a[0]), "r"(a[1]), "r"(a[2]), "r"(a[3]), "r"(b[0]), "r"(b[1]));
}
#define SW128(o) ((o) ^ (((o) >> 3) & 0x70))

__device__ __forceinline__ uint32_t pack_bf16_hi(float v0, float v1) {
    unsigned short h0 = __bfloat16_as_ushort(__float2bfloat16(v0));
    unsigned short h1 = __bfloat16_as_ushort(__float2bfloat16(v1));
    return (uint32_t)h0 | ((uint32_t)h1 << 16);
}
__device__ __forceinline__ uint32_t pack_bf16_lo(float v0, float v1, uint32_t hi) {
    float h0 = __bfloat162float(__ushort_as_bfloat16((unsigned short)(hi & 0xFFFF)));
    float h1 = __bfloat162float(__ushort_as_bfloat16((unsigned short)(hi >> 16)));
    unsigned short l0 = __bfloat16_as_ushort(__float2bfloat16(v0 - h0));
    unsigned short l1 = __bfloat16_as_ushort(__float2bfloat16(v1 - h1));
    return (uint32_t)l0 | ((uint32_t)l1 << 16);
}

// ---------------------------------------------------------------------------
// Kernel 0: copy former+latter into out channels [0,128), zero shift [128,192)
// ---------------------------------------------------------------------------
__global__ void k_init_out(const float* __restrict__ x, float* __restrict__ out) {
    int idx = blockIdx.x * blockDim.x + threadIdx.x;
    const int total = BB * 192 * LL;
    if (idx >= total) return;
    int b  = idx / (192 * LL);
    int r  = idx - b * (192 * LL);
    int ch = r >> 12;
    int l  = r & (LL - 1);
    float v = 0.0f;
    if (ch < 128) v = x[((size_t)b * 128 + ch) * LL + l];
    out[idx] = v;
}

// ---------------------------------------------------------------------------
// Kernel 0b: convert former to bf16 hi/lo planes (packed pairs)
// ---------------------------------------------------------------------------
__global__ void k_fconv(const float* __restrict__ x) {
    int p = blockIdx.x * blockDim.x + threadIdx.x;   // pair index
    const int total = BB * 64 * (LL / 2);
    if (p >= total) return;
    int b   = p / (64 * (LL / 2));
    int rem = p - b * (64 * (LL / 2));
    int ch  = rem / (LL / 2);
    int cp  = rem - ch * (LL / 2);
    const float* src = x + ((size_t)(b * 128 + ch)) * LL + cp * 2;
    float v0 = src[0], v1 = src[1];
    uint32_t hi = pack_bf16_hi(v0, v1);
    g_Fbh32[p] = hi;
    g_Fbl32[p] = pack_bf16_lo(v0, v1, hi);
}

// ---------------------------------------------------------------------------
// Kernel 1: per-(b,k) inverse norm of latter column, and flags from mask
// ---------------------------------------------------------------------------
__global__ void k_prep(const float* __restrict__ x, const float* __restrict__ mask) {
    int t = blockIdx.x * blockDim.x + threadIdx.x;
    if (t >= BB * LL) return;
    int b = t >> 12;
    int k = t & (LL - 1);
    const float* lat = x + ((size_t)b * 128 + 64) * LL;
    float s = 0.0f;
    #pragma unroll
    for (int c = 0; c < CC; c++) {
        float v = lat[(size_t)c * LL + k];
        s += v * v;
    }
    g_invn[t] = 1.0f / fmaxf(sqrtf(s), 1e-4f);
    if (t < LL) g_flag[t] = (mask[t] > 0.5f) ? 1 : 0;
}

// ---------------------------------------------------------------------------
// Kernel 1b: deterministic compaction of flagged indices (single block)
// ---------------------------------------------------------------------------
__global__ void k_compact() {
    __shared__ int cnt[256];
    int t = threadIdx.x;
    int base_l = t * 16;
    int c = 0;
    #pragma unroll
    for (int j = 0; j < 16; j++) c += g_flag[base_l + j];
    cnt[t] = c;
    __syncthreads();
    for (int off = 1; off < 256; off <<= 1) {
        int v = (t >= off) ? cnt[t - off] : 0;
        __syncthreads();
        cnt[t] += v;
        __syncthreads();
    }
    int pos = cnt[t] - c;
    for (int j = 0; j < 16; j++) {
        int l = base_l + j;
        if (g_flag[l]) g_list[pos++] = l;
    }
    if (t == 255) g_nflag = cnt[255];
}

// ---------------------------------------------------------------------------
// Kernel 2: mma.sync bf16x3 score GEMM (unchanged, proven).
// ---------------------------------------------------------------------------
#define SM_AHI    0
#define SM_ALO    16384
#define SM_BHI    32768
#define SM_BLO    49152
#define SM_INVN   65536
#define SM_DYN    66048

__global__ __launch_bounds__(256) void k_gemm_mma(const float* __restrict__ x) {
    extern __shared__ char smem[];
    uint32_t sbase = smem_u32(smem);
    int tid  = threadIdx.x;
    int n0 = blockIdx.x * 128;
    int m0 = blockIdx.y * 128;
    int b  = blockIdx.z;

    const float* lat = x + ((size_t)b * 128 + 64) * LL;
    float* invn_s = (float*)(smem + SM_INVN);
    if (tid < 128) invn_s[tid] = g_invn[b * LL + n0 + tid];

    {
        int side = tid >> 7;                  // 0 = A, 1 = B
        int r    = tid & 127;
        const float* src = lat + (side ? n0 : m0) + r;
        char* dhi = smem + (side ? SM_BHI : SM_AHI);
        char* dlo = smem + (side ? SM_BLO : SM_ALO);
        #pragma unroll 8
        for (int c0 = 0; c0 < CC; c0 += 2) {
            float v0 = src[(size_t)c0 * LL];
            float v1 = src[(size_t)(c0 + 1) * LL];
            uint32_t hi = pack_bf16_hi(v0, v1);
            uint32_t lo = pack_bf16_lo(v0, v1, hi);
            uint32_t off = SW128((uint32_t)(r * 128 + c0 * 2));
            *(uint32_t*)(dhi + off) = hi;
            *(uint32_t*)(dlo + off) = lo;
        }
    }
    __syncthreads();

    int wid  = tid >> 5;
    int lane = tid & 31;
    int wm = (wid & 3) * 32;
    int wn = (wid >> 2) * 64;
    int j  = lane & 7;
    int g  = lane >> 3;

    float acc[2][8][4];
    #pragma unroll
    for (int mi = 0; mi < 2; mi++)
        #pragma unroll
        for (int t = 0; t < 8; t++)
            #pragma unroll
            for (int q = 0; q < 4; q++) acc[mi][t][q] = 0.0f;

    #pragma unroll
    for (int kc = 0; kc < 4; kc++) {
        int kb = kc * 32;

        uint32_t a_hi[2][4], a_lo[2][4], b_hi[4][4], b_lo[4][4];
        #pragma unroll
        for (int mi = 0; mi < 2; mi++) {
            uint32_t row = wm + mi * 16 + (g & 1) * 8 + j;
            uint32_t kby = kb + (g >> 1) * 16;
            uint32_t off = SW128(row * 128 + kby);
            ldsm_x4(a_hi[mi], sbase + SM_AHI + off);
            ldsm_x4(a_lo[mi], sbase + SM_ALO + off);
        }
        #pragma unroll
        for (int tp = 0; tp < 4; tp++) {
            uint32_t row = wn + tp * 16 + (g >> 1) * 8 + j;
            uint32_t kby = kb + (g & 1) * 16;
            uint32_t off = SW128(row * 128 + kby);
            ldsm_x4(b_hi[tp], sbase + SM_BHI + off);
            ldsm_x4(b_lo[tp], sbase + SM_BLO + off);
        }

        #pragma unroll
        for (int mi = 0; mi < 2; mi++)
            #pragma unroll
            for (int t = 0; t < 8; t++) {
                const uint32_t* bh = &b_hi[t >> 1][(t & 1) * 2];
                const uint32_t* bl = &b_lo[t >> 1][(t & 1) * 2];
                mma_bf16(acc[mi][t], a_hi[mi], bh);
                mma_bf16(acc[mi][t], a_hi[mi], bl);
                mma_bf16(acc[mi][t], a_lo[mi], bh);
            }
    }

    float* Sp = g_S + (size_t)b * LL * LL;
    #pragma unroll
    for (int t = 0; t < 8; t++) {
        int n = wn + t * 8 + (lane & 3) * 2;
        float2 w = *(float2*)&invn_s[n];
        #pragma unroll
        for (int mi = 0; mi < 2; mi++) {
            int r0 = m0 + wm + mi * 16 + (lane >> 2);
            float* p0 = &Sp[(size_t)r0 * LL + n0 + n];
            float* p1 = &Sp[(size_t)(r0 + 8) * LL + n0 + n];
            *(float2*)p0 = make_float2(acc[mi][t][0] * w.x, acc[mi][t][1] * w.y);
            *(float2*)p1 = make_float2(acc[mi][t][2] * w.x, acc[mi][t][3] * w.y);
        }
    }
}

// ---------------------------------------------------------------------------
// Kernel 3: per flagged row: 9-point fused gather (coalesced) + masked softmax;
// write normalized attn row as bf16 hi/lo planes.
// ---------------------------------------------------------------------------
__global__ __launch_bounds__(256) void k_softmax() {
    int ii = blockIdx.x;
    if (ii >= g_nflag) return;
    int l = g_list[ii];
    int b = blockIdx.y;

    __shared__ float row[LL];
    __shared__ float red[256];

    const float* S = g_S + (size_t)b * LL * LL;
    int tid = threadIdx.x;

    int hl = l >> 6, wl = l & 63;
    int ml = (wl << 6) | hl;

    const float* rp[3][3];
    bool rv[3][3];
    #pragma unroll
    for (int ei = 0; ei < 3; ei++) {
        int m2 = ml + ei - 1;
        bool v = (m2 >= 0 && m2 < LL);
        int l2v = v ? (((m2 & 63) << 6) | (m2 >> 6)) : 0;
        #pragma unroll
        for (int di = 0; di < 3; di++) {
            int r = l2v + di - 1;
            bool ok = v && (r >= 0 && r < LL);
            rv[ei][di] = ok;
            rp[ei][di] = ok ? (S + (size_t)r * LL) : S;
        }
    }

    float mx = -INFINITY;
    #pragma unroll 4
    for (int k = tid; k < LL; k += 256) {
        int h = k >> 6, w = k & 63;
        float acc = 0.0f;
        #pragma unroll
        for (int ei = 0; ei < 3; ei++) {
            int hh = h + ei - 1;
            int k2;
            bool kv;
            if (hh >= 0 && hh < 64) { k2 = (hh << 6) | w; kv = true; }
            else if (hh < 0)        { k2 = 4032 + (w - 1); kv = (w >= 1); }
            else                    { k2 = w + 1;          kv = (w <= 62); }
            if (!kv) continue;
            #pragma unroll
            for (int di = 0; di < 3; di++) {
                int c = k2 + di - 1;
                if (rv[ei][di] && c >= 0 && c < LL)
                    acc += rp[ei][di][c];
            }
        }
        float val = g_flag[k] ? -INFINITY : acc;
        row[k] = val;
        mx = fmaxf(mx, val);
    }

    red[tid] = mx;
    __syncthreads();
    #pragma unroll
    for (int s = 128; s > 0; s >>= 1) {
        if (tid < s) red[tid] = fmaxf(red[tid], red[tid + s]);
        __syncthreads();
    }
    mx = red[0];
    __syncthreads();

    float sum = 0.0f;
    for (int k = tid; k < LL; k += 256) {
        float v = row[k];
        float e = (v == -INFINITY) ? 0.0f : __expf(v - mx);
        row[k] = e;
        sum += e;
    }
    red[tid] = sum;
    __syncthreads();
    #pragma unroll
    for (int s = 128; s > 0; s >>= 1) {
        if (tid < s) red[tid] += red[tid + s];
        __syncthreads();
    }
    float inv = 1.0f / red[0];
    __syncthreads();

    size_t base = ((size_t)b * LL + ii) * LL / 2;
    for (int kp = tid; kp < LL / 2; kp += 256) {
        float v0 = row[2 * kp] * inv;
        float v1 = row[2 * kp + 1] * inv;
        uint32_t hi = pack_bf16_hi(v0, v1);
        g_Pbh32[base + kp] = hi;
        g_Pbl32[base + kp] = pack_bf16_lo(v0, v1, hi);
    }
}

// ---------------------------------------------------------------------------
// Kernel 4a: shift GEMM stage 1 (tensor cores, K-split 4, partials).
// partial[b][ks][i0+row][ch] = sum_{k in slice ks} P[row][k] * F[ch][k]
// M tile = 64 P-rows, N = 64 ch, K-slice = 1024 (16 chunks of 64).
// ---------------------------------------------------------------------------
#define SH_PH 0
#define SH_PL 8192
#define SH_FH 16384
#define SH_FL 24576

__global__ __launch_bounds__(256) void k_shift1() {
    __shared__ char smem[32768];
    uint32_t sbase = smem_u32(smem);

    int i0 = blockIdx.x * 64;
    int ks = blockIdx.y;
    int b  = blockIdx.z;
    if (i0 >= g_nflag) return;

    int tid  = threadIdx.x;
    int wid  = tid >> 5;
    int lane = tid & 31;
    int wm = (wid >> 1) * 16;   // M offset (4 groups of 16)
    int wn = (wid & 1) * 32;    // N offset (2 groups of 32)
    int j  = lane & 7;
    int g  = lane >> 3;

    float acc[4][4];
    #pragma unroll
    for (int t = 0; t < 4; t++)
        #pragma unroll
        for (int q = 0; q < 4; q++) acc[t][q] = 0.0f;

    for (int kc = 0; kc < 16; kc++) {
        int kb0 = ks * 1024 + kc * 64;
        __syncthreads();
        // load P tile (64 rows x 64 k) and F tile (64 ch x 64 k), both planes
        #pragma unroll
        for (int i = 0; i < 8; i++) {
            int e  = tid + i * 256;
            int r  = e >> 5;          // 0..63
            int cp = e & 31;          // uint32 pair within row
            size_t pidx = ((size_t)(b * LL + i0 + r) * LL + kb0) / 2 + cp;
            size_t fidx = ((size_t)(b * 64 + r) * LL + kb0) / 2 + cp;
            uint32_t off = SW128((uint32_t)(r * 128 + cp * 4));
            *(uint32_t*)(smem + SH_PH + off) = g_Pbh32[pidx];
            *(uint32_t*)(smem + SH_PL + off) = g_Pbl32[pidx];
            *(uint32_t*)(smem + SH_FH + off) = g_Fbh32[fidx];
            *(uint32_t*)(smem + SH_FL + off) = g_Fbl32[fidx];
        }
        __syncthreads();

        #pragma unroll
        for (int ksub = 0; ksub < 4; ksub++) {
            int kb = ksub * 32;
            uint32_t a_hi[4], a_lo[4], b_hi[2][4], b_lo[2][4];
            {
                uint32_t row = wm + (g & 1) * 8 + j;
                uint32_t off = SW128(row * 128 + kb + (g >> 1) * 16);
                ldsm_x4(a_hi, sbase + SH_PH + off);
                ldsm_x4(a_lo, sbase + SH_PL + off);
            }
            #pragma unroll
            for (int tp = 0; tp < 2; tp++) {
                uint32_t row = wn + tp * 16 + (g >> 1) * 8 + j;
                uint32_t off = SW128(row * 128 + kb + (g & 1) * 16);
                ldsm_x4(b_hi[tp], sbase + SH_FH + off);
                ldsm_x4(b_lo[tp], sbase + SH_FL + off);
            }
            #pragma unroll
            for (int t = 0; t < 4; t++) {
                const uint32_t* bh = &b_hi[t >> 1][(t & 1) * 2];
                const uint32_t* bl = &b_lo[t >> 1][(t & 1) * 2];
                mma_bf16(acc[t], a_hi, bh);
                mma_bf16(acc[t], a_hi, bl);
                mma_bf16(acc[t], a_lo, bh);
            }
        }
    }

    // store partials
    float* part = g_part + (size_t)(b * 4 + ks) * LL * 64;
    #pragma unroll
    for (int t = 0; t < 4; t++) {
        #pragma unroll
        for (int q = 0; q < 4; q++) {
            int row = wm + (lane >> 2) + ((q >= 2) ? 8 : 0);
            int ch  = wn + t * 8 + (lane & 3) * 2 + (q & 1);
            part[(size_t)(i0 + row) * 64 + ch] = acc[t][q];
        }
    }
}

// ---------------------------------------------------------------------------
// Kernel 4b: shift stage 2 — sum 4 K-split partials, scatter to out.
// ---------------------------------------------------------------------------
__global__ __launch_bounds__(256) void k_shift2(float* __restrict__ out) {
    int idx = blockIdx.x * 256 + threadIdx.x;     // b * LL * 64 total
    int ch = idx & 63;
    int ii = (idx >> 6) & (LL - 1);
    int b  = idx >> 18;
    if (ii >= g_nflag) return;
    float s = 0.0f;
    #pragma unroll
    for (int ks = 0; ks < 4; ks++)
        s += g_part[(size_t)(b * 4 + ks) * LL * 64 + (size_t)ii * 64 + ch];
    int l = g_list[ii];
    out[((size_t)b * 192 + 128 + ch) * LL + l] = s;
}

// ---------------------------------------------------------------------------
extern "C" void kernel_launch(void* const* d_in, const int* in_sizes, int n_in,
                              void* d_out, int out_size) {
    const float* x    = (const float*)d_in[0];   // (2,128,64,64)
    const float* mask = (const float*)d_in[1];   // (1,1,64,64)
    float* out = (float*)d_out;                  // (2,192,64,64)

    {
        int total = BB * 192 * LL;
        k_init_out<<<(total + 255) / 256, 256>>>(x, out);
    }
    {
        int total = BB * 64 * (LL / 2);
        k_fconv<<<(total + 255) / 256, 256>>>(x);
    }
    {
        int total = BB * LL;
        k_prep<<<(total + 255) / 256, 256>>>(x, mask);
    }
    k_compact<<<1, 256>>>();
    {
        cudaFuncSetAttribute(k_gemm_mma, cudaFuncAttributeMaxDynamicSharedMemorySize, SM_DYN);
        dim3 grid(LL / 128, LL / 128, BB);
        k_gemm_mma<<<grid, 256, SM_DYN>>>(x);
    }
    {
        dim3 grid(LL, BB);
        k_softmax<<<grid, 256>>>();
    }
    {
        dim3 grid(LL / 64, 4, BB);   // M-tiles x K-split x batch
        k_shift1<<<grid, 256>>>();
    }
    {
        int total = BB * LL * 64;
        k_shift2<<<total / 256, 256>>>(out);
    }
}

// round 8
// speedup vs baseline: 1.8606x; 1.0870x over previous
#include <cuda_runtime.h>
#include <cuda_bf16.h>
#include <cstdint>
#include <math.h>

// Problem constants (fixed shapes from setup_inputs)
#define BB 2
#define CC 64
#define LL 4096   // H*W = 64*64

// Scratch
__device__ float    g_S[(size_t)BB * LL * LL];          // score matrix, 128 MiB
__device__ uint32_t g_Pbh32[(size_t)BB * LL * LL / 2];  // attn rows bf16 hi (packed pairs)
__device__ uint32_t g_Pbl32[(size_t)BB * LL * LL / 2];  // attn rows bf16 lo
__device__ uint32_t g_Fbh32[(size_t)BB * 64 * LL / 2];  // former bf16 hi
__device__ uint32_t g_Fbl32[(size_t)BB * 64 * LL / 2];  // former bf16 lo
__device__ float    g_part[(size_t)BB * 4 * LL * 64];   // K-split partials, 8 MiB
__device__ float    g_invn[BB * LL];
__device__ int      g_flag[LL];
__device__ int      g_list[LL];
__device__ int      g_nflag;

// ---------------------------------------------------------------------------
// mma.sync helpers (arch-agnostic: sm_80+ PTX, no tcgen05)
// ---------------------------------------------------------------------------
__device__ __forceinline__ uint32_t smem_u32(const void* p) {
    uint32_t a;
    asm("{ .reg .u64 t; cvta.to.shared.u64 t, %1; cvt.u32.u64 %0, t; }"
        : "=r"(a) : "l"(p));
    return a;
}
__device__ __forceinline__ void ldsm_x4(uint32_t* r, uint32_t addr) {
    asm volatile("ldmatrix.sync.aligned.m8n8.x4.shared.b16 {%0,%1,%2,%3}, [%4];"
                 : "=r"(r[0]), "=r"(r[1]), "=r"(r[2]), "=r"(r[3]) : "r"(addr));
}
__device__ __forceinline__ void mma_bf16(float* d, const uint32_t* a, const uint32_t* b) {
    asm volatile(
        "mma.sync.aligned.m16n8k16.row.col.f32.bf16.bf16.f32 "
        "{%0,%1,%2,%3}, {%4,%5,%6,%7}, {%8,%9}, {%0,%1,%2,%3};"
        : "+f"(d[0]), "+f"(d[1]), "+f"(d[2]), "+f"(d[3])
        : "r"(a[0]), "r"(a[1]), "r"(a[2]), "r"(a[3]), "r"(b[0]), "r"(b[1]));
}
#define SW128(o) ((o) ^ (((o) >> 3) & 0x70))

__device__ __forceinline__ uint32_t pack_bf16_hi(float v0, float v1) {
    unsigned short h0 = __bfloat16_as_ushort(__float2bfloat16(v0));
    unsigned short h1 = __bfloat16_as_ushort(__float2bfloat16(v1));
    return (uint32_t)h0 | ((uint32_t)h1 << 16);
}
__device__ __forceinline__ uint32_t pack_bf16_lo(float v0, float v1, uint32_t hi) {
    float h0 = __bfloat162float(__ushort_as_bfloat16((unsigned short)(hi & 0xFFFF)));
    float h1 = __bfloat162float(__ushort_as_bfloat16((unsigned short)(hi >> 16)));
    unsigned short l0 = __bfloat16_as_ushort(__float2bfloat16(v0 - h0));
    unsigned short l1 = __bfloat16_as_ushort(__float2bfloat16(v1 - h1));
    return (uint32_t)l0 | ((uint32_t)l1 << 16);
}

// ---------------------------------------------------------------------------
// Kernel 0: copy former+latter into out channels [0,128), zero shift [128,192)
// ---------------------------------------------------------------------------
__global__ void k_init_out(const float* __restrict__ x, float* __restrict__ out) {
    int idx = blockIdx.x * blockDim.x + threadIdx.x;
    const int total = BB * 192 * LL;
    if (idx >= total) return;
    int b  = idx / (192 * LL);
    int r  = idx - b * (192 * LL);
    int ch = r >> 12;
    int l  = r & (LL - 1);
    float v = 0.0f;
    if (ch < 128) v = x[((size_t)b * 128 + ch) * LL + l];
    out[idx] = v;
}

// ---------------------------------------------------------------------------
// Kernel 0b: convert former to bf16 hi/lo planes (packed pairs)
// ---------------------------------------------------------------------------
__global__ void k_fconv(const float* __restrict__ x) {
    int p = blockIdx.x * blockDim.x + threadIdx.x;   // pair index
    const int total = BB * 64 * (LL / 2);
    if (p >= total) return;
    int b   = p / (64 * (LL / 2));
    int rem = p - b * (64 * (LL / 2));
    int ch  = rem / (LL / 2);
    int cp  = rem - ch * (LL / 2);
    const float* src = x + ((size_t)(b * 128 + ch)) * LL + cp * 2;
    float v0 = src[0], v1 = src[1];
    uint32_t hi = pack_bf16_hi(v0, v1);
    g_Fbh32[p] = hi;
    g_Fbl32[p] = pack_bf16_lo(v0, v1, hi);
}

// ---------------------------------------------------------------------------
// Kernel 1: per-(b,k) inverse norm of latter column, and flags from mask
// ---------------------------------------------------------------------------
__global__ void k_prep(const float* __restrict__ x, const float* __restrict__ mask) {
    int t = blockIdx.x * blockDim.x + threadIdx.x;
    if (t >= BB * LL) return;
    int b = t >> 12;
    int k = t & (LL - 1);
    const float* lat = x + ((size_t)b * 128 + 64) * LL;
    float s = 0.0f;
    #pragma unroll
    for (int c = 0; c < CC; c++) {
        float v = lat[(size_t)c * LL + k];
        s += v * v;
    }
    g_invn[t] = 1.0f / fmaxf(sqrtf(s), 1e-4f);
    if (t < LL) g_flag[t] = (mask[t] > 0.5f) ? 1 : 0;
}

// ---------------------------------------------------------------------------
// Kernel 1b: deterministic compaction of flagged indices (single block)
// ---------------------------------------------------------------------------
__global__ void k_compact() {
    __shared__ int cnt[256];
    int t = threadIdx.x;
    int base_l = t * 16;
    int fl[16];
    #pragma unroll
    for (int q = 0; q < 4; q++) {
        int4 v = *(const int4*)&g_flag[base_l + q * 4];
        fl[q * 4 + 0] = v.x; fl[q * 4 + 1] = v.y;
        fl[q * 4 + 2] = v.z; fl[q * 4 + 3] = v.w;
    }
    int c = 0;
    #pragma unroll
    for (int j = 0; j < 16; j++) c += fl[j];
    cnt[t] = c;
    __syncthreads();
    for (int off = 1; off < 256; off <<= 1) {
        int v = (t >= off) ? cnt[t - off] : 0;
        __syncthreads();
        cnt[t] += v;
        __syncthreads();
    }
    int pos = cnt[t] - c;
    #pragma unroll
    for (int j = 0; j < 16; j++) {
        if (fl[j]) g_list[pos++] = base_l + j;
    }
    if (t == 255) g_nflag = cnt[255];
}

// ---------------------------------------------------------------------------
// Kernel 2: mma.sync bf16x3 score GEMM (unchanged, proven).
// ---------------------------------------------------------------------------
#define SM_AHI    0
#define SM_ALO    16384
#define SM_BHI    32768
#define SM_BLO    49152
#define SM_INVN   65536
#define SM_DYN    66048

__global__ __launch_bounds__(256) void k_gemm_mma(const float* __restrict__ x) {
    extern __shared__ char smem[];
    uint32_t sbase = smem_u32(smem);
    int tid  = threadIdx.x;
    int n0 = blockIdx.x * 128;
    int m0 = blockIdx.y * 128;
    int b  = blockIdx.z;

    const float* lat = x + ((size_t)b * 128 + 64) * LL;
    float* invn_s = (float*)(smem + SM_INVN);
    if (tid < 128) invn_s[tid] = g_invn[b * LL + n0 + tid];

    {
        int side = tid >> 7;                  // 0 = A, 1 = B
        int r    = tid & 127;
        const float* src = lat + (side ? n0 : m0) + r;
        char* dhi = smem + (side ? SM_BHI : SM_AHI);
        char* dlo = smem + (side ? SM_BLO : SM_ALO);
        #pragma unroll 8
        for (int c0 = 0; c0 < CC; c0 += 2) {
            float v0 = src[(size_t)c0 * LL];
            float v1 = src[(size_t)(c0 + 1) * LL];
            uint32_t hi = pack_bf16_hi(v0, v1);
            uint32_t lo = pack_bf16_lo(v0, v1, hi);
            uint32_t off = SW128((uint32_t)(r * 128 + c0 * 2));
            *(uint32_t*)(dhi + off) = hi;
            *(uint32_t*)(dlo + off) = lo;
        }
    }
    __syncthreads();

    int wid  = tid >> 5;
    int lane = tid & 31;
    int wm = (wid & 3) * 32;
    int wn = (wid >> 2) * 64;
    int j  = lane & 7;
    int g  = lane >> 3;

    float acc[2][8][4];
    #pragma unroll
    for (int mi = 0; mi < 2; mi++)
        #pragma unroll
        for (int t = 0; t < 8; t++)
            #pragma unroll
            for (int q = 0; q < 4; q++) acc[mi][t][q] = 0.0f;

    #pragma unroll
    for (int kc = 0; kc < 4; kc++) {
        int kb = kc * 32;

        uint32_t a_hi[2][4], a_lo[2][4], b_hi[4][4], b_lo[4][4];
        #pragma unroll
        for (int mi = 0; mi < 2; mi++) {
            uint32_t row = wm + mi * 16 + (g & 1) * 8 + j;
            uint32_t kby = kb + (g >> 1) * 16;
            uint32_t off = SW128(row * 128 + kby);
            ldsm_x4(a_hi[mi], sbase + SM_AHI + off);
            ldsm_x4(a_lo[mi], sbase + SM_ALO + off);
        }
        #pragma unroll
        for (int tp = 0; tp < 4; tp++) {
            uint32_t row = wn + tp * 16 + (g >> 1) * 8 + j;
            uint32_t kby = kb + (g & 1) * 16;
            uint32_t off = SW128(row * 128 + kby);
            ldsm_x4(b_hi[tp], sbase + SM_BHI + off);
            ldsm_x4(b_lo[tp], sbase + SM_BLO + off);
        }

        #pragma unroll
        for (int mi = 0; mi < 2; mi++)
            #pragma unroll
            for (int t = 0; t < 8; t++) {
                const uint32_t* bh = &b_hi[t >> 1][(t & 1) * 2];
                const uint32_t* bl = &b_lo[t >> 1][(t & 1) * 2];
                mma_bf16(acc[mi][t], a_hi[mi], bh);
                mma_bf16(acc[mi][t], a_hi[mi], bl);
                mma_bf16(acc[mi][t], a_lo[mi], bh);
            }
    }

    float* Sp = g_S + (size_t)b * LL * LL;
    #pragma unroll
    for (int t = 0; t < 8; t++) {
        int n = wn + t * 8 + (lane & 3) * 2;
        float2 w = *(float2*)&invn_s[n];
        #pragma unroll
        for (int mi = 0; mi < 2; mi++) {
            int r0 = m0 + wm + mi * 16 + (lane >> 2);
            float* p0 = &Sp[(size_t)r0 * LL + n0 + n];
            float* p1 = &Sp[(size_t)(r0 + 8) * LL + n0 + n];
            *(float2*)p0 = make_float2(acc[mi][t][0] * w.x, acc[mi][t][1] * w.y);
            *(float2*)p1 = make_float2(acc[mi][t][2] * w.x, acc[mi][t][3] * w.y);
        }
    }
}

// ---------------------------------------------------------------------------
// Kernel 3: per flagged row: 9-point fused gather, 4-wide vectorized + masked
// softmax; write normalized attn row as bf16 hi/lo planes.
//
// For 4 consecutive k (same h since 4|64) and term (ei,di):
//   interior (hh in [0,64)): k2 = hh*64+w0 (4-aligned); columns needed are
//   k2-1..k2+4; the aligned float4 [k2..k2+3] is ALWAYS in-bounds; only the
//   two edge scalars need predicates.  Boundary hh (-1 / 64) keeps the exact
//   scalar path of the previous (passing) kernel.
// ---------------------------------------------------------------------------
__global__ __launch_bounds__(256) void k_softmax() {
    int ii = blockIdx.x;
    if (ii >= g_nflag) return;
    int l = g_list[ii];
    int b = blockIdx.y;

    __shared__ float row[LL];
    __shared__ float red[256];

    const float* S = g_S + (size_t)b * LL * LL;
    int tid = threadIdx.x;

    // row-side shifted indices (flat-boundary semantics)
    int hl = l >> 6, wl = l & 63;
    int ml = (wl << 6) | hl;

    const float* rp[3][3];
    bool rv[3][3];
    #pragma unroll
    for (int ei = 0; ei < 3; ei++) {
        int m2 = ml + ei - 1;
        bool v = (m2 >= 0 && m2 < LL);
        int l2v = v ? (((m2 & 63) << 6) | (m2 >> 6)) : 0;
        #pragma unroll
        for (int di = 0; di < 3; di++) {
            int r = l2v + di - 1;
            bool ok = v && (r >= 0 && r < LL);
            rv[ei][di] = ok;
            rp[ei][di] = ok ? (S + (size_t)r * LL) : S;
        }
    }

    float mx = -INFINITY;
    for (int idx = tid; idx < LL / 4; idx += 256) {
        int k0 = idx * 4;
        int h  = k0 >> 6;
        int w0 = k0 & 63;
        float a0 = 0.f, a1 = 0.f, a2 = 0.f, a3 = 0.f;

        #pragma unroll
        for (int ei = 0; ei < 3; ei++) {
            int hh = h + ei - 1;
            if (hh >= 0 && hh < 64) {
                int k2 = (hh << 6) | w0;
                #pragma unroll
                for (int di = 0; di < 3; di++) {
                    if (!rv[ei][di]) continue;
                    const float* rw = rp[ei][di];
                    float4 v = *(const float4*)&rw[k2];
                    if (di == 0) {
                        float vl = (k2 >= 1) ? rw[k2 - 1] : 0.0f;
                        a0 += vl;  a1 += v.x; a2 += v.y; a3 += v.z;
                    } else if (di == 1) {
                        a0 += v.x; a1 += v.y; a2 += v.z; a3 += v.w;
                    } else {
                        float vr = (k2 + 4 < LL) ? rw[k2 + 4] : 0.0f;
                        a0 += v.y; a1 += v.z; a2 += v.w; a3 += vr;
                    }
                }
            } else {
                // boundary path (exact scalar semantics)
                bool neg = (hh < 0);
                float* accp[4] = {&a0, &a1, &a2, &a3};
                #pragma unroll
                for (int j = 0; j < 4; j++) {
                    int w = w0 + j;
                    int k2; bool kv;
                    if (neg) { k2 = 4032 + (w - 1); kv = (w >= 1); }
                    else     { k2 = w + 1;          kv = (w <= 62); }
                    if (!kv) continue;
                    #pragma unroll
                    for (int di = 0; di < 3; di++) {
                        int c = k2 + di - 1;
                        if (rv[ei][di] && c >= 0 && c < LL)
                            *accp[j] += rp[ei][di][c];
                    }
                }
            }
        }

        int4 fl = *(const int4*)&g_flag[k0];
        float v0 = fl.x ? -INFINITY : a0;
        float v1 = fl.y ? -INFINITY : a1;
        float v2 = fl.z ? -INFINITY : a2;
        float v3 = fl.w ? -INFINITY : a3;
        *(float4*)&row[k0] = make_float4(v0, v1, v2, v3);
        mx = fmaxf(mx, fmaxf(fmaxf(v0, v1), fmaxf(v2, v3)));
    }

    red[tid] = mx;
    __syncthreads();
    #pragma unroll
    for (int s = 128; s > 0; s >>= 1) {
        if (tid < s) red[tid] = fmaxf(red[tid], red[tid + s]);
        __syncthreads();
    }
    mx = red[0];
    __syncthreads();

    float sum = 0.0f;
    for (int k = tid; k < LL; k += 256) {
        float v = row[k];
        float e = (v == -INFINITY) ? 0.0f : __expf(v - mx);
        row[k] = e;
        sum += e;
    }
    red[tid] = sum;
    __syncthreads();
    #pragma unroll
    for (int s = 128; s > 0; s >>= 1) {
        if (tid < s) red[tid] += red[tid + s];
        __syncthreads();
    }
    float inv = 1.0f / red[0];
    __syncthreads();

    size_t base = ((size_t)b * LL + ii) * LL / 2;
    for (int kp = tid; kp < LL / 2; kp += 256) {
        float v0 = row[2 * kp] * inv;
        float v1 = row[2 * kp + 1] * inv;
        uint32_t hi = pack_bf16_hi(v0, v1);
        g_Pbh32[base + kp] = hi;
        g_Pbl32[base + kp] = pack_bf16_lo(v0, v1, hi);
    }
}

// ---------------------------------------------------------------------------
// Kernel 4a: shift GEMM stage 1 (tensor cores, K-split 4, partials).
// ---------------------------------------------------------------------------
#define SH_PH 0
#define SH_PL 8192
#define SH_FH 16384
#define SH_FL 24576

__global__ __launch_bounds__(256) void k_shift1() {
    __shared__ char smem[32768];
    uint32_t sbase = smem_u32(smem);

    int i0 = blockIdx.x * 64;
    int ks = blockIdx.y;
    int b  = blockIdx.z;
    if (i0 >= g_nflag) return;

    int tid  = threadIdx.x;
    int wid  = tid >> 5;
    int lane = tid & 31;
    int wm = (wid >> 1) * 16;
    int wn = (wid & 1) * 32;
    int j  = lane & 7;
    int g  = lane >> 3;

    float acc[4][4];
    #pragma unroll
    for (int t = 0; t < 4; t++)
        #pragma unroll
        for (int q = 0; q < 4; q++) acc[t][q] = 0.0f;

    for (int kc = 0; kc < 16; kc++) {
        int kb0 = ks * 1024 + kc * 64;
        __syncthreads();
        #pragma unroll
        for (int i = 0; i < 8; i++) {
            int e  = tid + i * 256;
            int r  = e >> 5;
            int cp = e & 31;
            size_t pidx = ((size_t)(b * LL + i0 + r) * LL + kb0) / 2 + cp;
            size_t fidx = ((size_t)(b * 64 + r) * LL + kb0) / 2 + cp;
            uint32_t off = SW128((uint32_t)(r * 128 + cp * 4));
            *(uint32_t*)(smem + SH_PH + off) = g_Pbh32[pidx];
            *(uint32_t*)(smem + SH_PL + off) = g_Pbl32[pidx];
            *(uint32_t*)(smem + SH_FH + off) = g_Fbh32[fidx];
            *(uint32_t*)(smem + SH_FL + off) = g_Fbl32[fidx];
        }
        __syncthreads();

        #pragma unroll
        for (int ksub = 0; ksub < 4; ksub++) {
            int kb = ksub * 32;
            uint32_t a_hi[4], a_lo[4], b_hi[2][4], b_lo[2][4];
            {
                uint32_t row = wm + (g & 1) * 8 + j;
                uint32_t off = SW128(row * 128 + kb + (g >> 1) * 16);
                ldsm_x4(a_hi, sbase + SH_PH + off);
                ldsm_x4(a_lo, sbase + SH_PL + off);
            }
            #pragma unroll
            for (int tp = 0; tp < 2; tp++) {
                uint32_t row = wn + tp * 16 + (g >> 1) * 8 + j;
                uint32_t off = SW128(row * 128 + kb + (g & 1) * 16);
                ldsm_x4(b_hi[tp], sbase + SH_FH + off);
                ldsm_x4(b_lo[tp], sbase + SH_FL + off);
            }
            #pragma unroll
            for (int t = 0; t < 4; t++) {
                const uint32_t* bh = &b_hi[t >> 1][(t & 1) * 2];
                const uint32_t* bl = &b_lo[t >> 1][(t & 1) * 2];
                mma_bf16(acc[t], a_hi, bh);
                mma_bf16(acc[t], a_hi, bl);
                mma_bf16(acc[t], a_lo, bh);
            }
        }
    }

    float* part = g_part + (size_t)(b * 4 + ks) * LL * 64;
    #pragma unroll
    for (int t = 0; t < 4; t++) {
        #pragma unroll
        for (int q = 0; q < 4; q++) {
            int row = wm + (lane >> 2) + ((q >= 2) ? 8 : 0);
            int ch  = wn + t * 8 + (lane & 3) * 2 + (q & 1);
            part[(size_t)(i0 + row) * 64 + ch] = acc[t][q];
        }
    }
}

// ---------------------------------------------------------------------------
// Kernel 4b: shift stage 2 — sum 4 K-split partials, scatter to out.
// ---------------------------------------------------------------------------
__global__ __launch_bounds__(256) void k_shift2(float* __restrict__ out) {
    int idx = blockIdx.x * 256 + threadIdx.x;
    int ch = idx & 63;
    int ii = (idx >> 6) & (LL - 1);
    int b  = idx >> 18;
    if (ii >= g_nflag) return;
    float s = 0.0f;
    #pragma unroll
    for (int ks = 0; ks < 4; ks++)
        s += g_part[(size_t)(b * 4 + ks) * LL * 64 + (size_t)ii * 64 + ch];
    int l = g_list[ii];
    out[((size_t)b * 192 + 128 + ch) * LL + l] = s;
}

// ---------------------------------------------------------------------------
extern "C" void kernel_launch(void* const* d_in, const int* in_sizes, int n_in,
                              void* d_out, int out_size) {
    const float* x    = (const float*)d_in[0];   // (2,128,64,64)
    const float* mask = (const float*)d_in[1];   // (1,1,64,64)
    float* out = (float*)d_out;                  // (2,192,64,64)

    {
        int total = BB * 192 * LL;
        k_init_out<<<(total + 255) / 256, 256>>>(x, out);
    }
    {
        int total = BB * 64 * (LL / 2);
        k_fconv<<<(total + 255) / 256, 256>>>(x);
    }
    {
        int total = BB * LL;
        k_prep<<<(total + 255) / 256, 256>>>(x, mask);
    }
    k_compact<<<1, 256>>>();
    {
        cudaFuncSetAttribute(k_gemm_mma, cudaFuncAttributeMaxDynamicSharedMemorySize, SM_DYN);
        dim3 grid(LL / 128, LL / 128, BB);
        k_gemm_mma<<<grid, 256, SM_DYN>>>(x);
    }
    {
        dim3 grid(LL, BB);
        k_softmax<<<grid, 256>>>();
    }
    {
        dim3 grid(LL / 64, 4, BB);
        k_shift1<<<grid, 256>>>();
    }
    {
        int total = BB * LL * 64;
        k_shift2<<<total / 256, 256>>>(out);
    }
}